// round 13
// baseline (speedup 1.0000x reference)
#include <cuda_runtime.h>
#include <math.h>
#include <stdint.h>

#define BATCH 32
#define NPTS  128
#define DIM   2048
#define HID   1024
#define MROWS (BATCH * NPTS)   // 4096
#define KC    32               // K floats per smem chunk (= 128B SW128 atom row)
#define BNT   256              // GEMM N tile
#define FULLM 0xffffffffu

// tcgen05 / f32x2 only exist in the sm_103a (arch-specific) compilation pass.
#ifdef __CUDA_ARCH_FEAT_SM103_ALL
#define HAS_TCGEN05 1
#endif

// ------------------------------ scratch ------------------------------------
__device__ float d_cost[BATCH * NPTS * NPTS];
__device__ int   d_perm[MROWS];                 // d_perm[g] = global src row of out1 row g
__device__ float d_h[2u * MROWS * HID];         // hidden acts: rows 0..4095 support, 4096..8191 query
__device__ float d_tmp[(size_t)MROWS * DIM];    // query + mlp(query), unpermuted

// ------------------------------ PTX helpers ---------------------------------
__device__ __forceinline__ uint32_t smem_u32(const void* p) {
    uint32_t a;
    asm("{ .reg .u64 t; cvta.to.shared.u64 t, %1; cvt.u32.u64 %0, t; }"
        : "=r"(a) : "l"(p));
    return a;
}
#define SW128(o) ((o) ^ (((o) >> 3) & 0x70))

#ifdef HAS_TCGEN05
__device__ __forceinline__ float to_tf32(float x) {
    float r; asm("cvt.rna.tf32.f32 %0, %1;" : "=f"(r) : "f"(x)); return r;
}
#define TCGEN05_ALLOC(smem_addr, nCols) \
    asm volatile("tcgen05.alloc.cta_group::1.sync.aligned.shared::cta.b32 [%0], %1;" \
        :: "r"((uint32_t)(smem_addr)), "r"((uint32_t)(nCols)) : "memory")
#define TCGEN05_DEALLOC(tmem_addr, nCols) \
    asm volatile("tcgen05.dealloc.cta_group::1.sync.aligned.b32 %0, %1;" \
        :: "r"(tmem_addr), "r"((uint32_t)(nCols)))
#define TCGEN05_RELINQUISH() \
    asm volatile("tcgen05.relinquish_alloc_permit.cta_group::1.sync.aligned;")
#define TCGEN05_COMMIT(mbar) \
    asm volatile("tcgen05.commit.cta_group::1.mbarrier::arrive::one.shared::cluster.b64 [%0];" \
        :: "r"((uint32_t)(mbar)) : "memory")
#define TCGEN05_FENCE_AFTER() \
    asm volatile("tcgen05.fence::after_thread_sync;" ::: "memory")
#define TCGEN05_FENCE_BEFORE() \
    asm volatile("tcgen05.fence::before_thread_sync;" ::: "memory")
#define TCGEN05_WAIT_LD() \
    asm volatile("tcgen05.wait::ld.sync.aligned;" ::: "memory")
#define TCGEN05_LD_32X32B_X16(r, tmem_addr) \
    asm volatile("tcgen05.ld.sync.aligned.32x32b.x16.b32 " \
        "{%0, %1, %2, %3, %4, %5, %6, %7, %8, %9, %10, %11, %12, %13, %14, %15}, [%16];" \
        : "=r"((r)[0]), "=r"((r)[1]), "=r"((r)[2]), "=r"((r)[3]), \
          "=r"((r)[4]), "=r"((r)[5]), "=r"((r)[6]), "=r"((r)[7]), \
          "=r"((r)[8]), "=r"((r)[9]), "=r"((r)[10]), "=r"((r)[11]), \
          "=r"((r)[12]), "=r"((r)[13]), "=r"((r)[14]), "=r"((r)[15]) \
        : "r"(tmem_addr))
#define MBARRIER_INIT(mbar, count) \
    asm volatile("mbarrier.init.shared.b64 [%0], %1;" \
        :: "r"((uint32_t)(mbar)), "r"((uint32_t)(count)) : "memory")
#define MBARRIER_WAIT_PARITY(mbar, parity) do { \
    uint32_t _m = (uint32_t)(mbar); uint32_t _p = (uint32_t)(parity); uint32_t _d; \
    asm volatile("{\n\t.reg .pred p;\n\t" \
        "mbarrier.try_wait.parity.acquire.cta.shared::cta.b64 p, [%1], %2;\n\t" \
        "selp.b32 %0, 1, 0, p;\n\t}" : "=r"(_d) : "r"(_m), "r"(_p) : "memory"); \
    if (!_d) { \
        asm volatile("{\n\t.reg .pred P1;\n\t" \
            "WL_%=:\n\t" \
            "mbarrier.try_wait.parity.acquire.cta.shared::cta.b64 P1, [%0], %1, 0x989680;\n\t" \
            "@P1 bra.uni WD_%=;\n\t" \
            "bra.uni WL_%=;\n\t" \
            "WD_%=:\n\t}" :: "r"(_m), "r"(_p) : "memory"); \
    } \
} while (0)

__device__ __forceinline__ void mma_tf32_ss(uint32_t d, uint64_t ad, uint64_t bd,
                                            uint32_t idesc, int acc) {
    asm volatile("{\n\t.reg .pred p;\n\t"
        "setp.ne.u32 p, %4, 0;\n\t"
        "tcgen05.mma.cta_group::1.kind::tf32 [%0], %1, %2, %3, {%5, %5, %5, %5}, p;\n\t"
        "}" :: "r"(d), "l"(ad), "l"(bd), "r"(idesc), "r"(acc), "r"(0u) : "memory");
}
// idesc: c=F32(1<<4), a=TF32(2<<7), b=TF32(2<<10), N=256(32<<17), M=128(8<<24)
#define IDESC_TF32 ((8u << 24) | ((BNT / 8u) << 17) | (2u << 10) | (2u << 7) | (1u << 4))

__device__ __forceinline__ uint64_t make_desc_sw128(uint32_t addr) {
    return ((uint64_t)2 << 61) | ((uint64_t)1 << 46) | ((uint64_t)64 << 32)
         | ((uint64_t)1 << 16) | ((addr >> 4) & 0x3FFF);
}

__device__ __forceinline__ void fma2(unsigned long long& d,
                                     unsigned long long a, unsigned long long b) {
    asm("fma.rn.f32x2 %0, %1, %2, %0;" : "+l"(d) : "l"(a), "l"(b));
}
#endif // HAS_TCGEN05

// ------------------------- cost (fp32) + fused norms -------------------------
__global__ void __launch_bounds__(256) cost_kernel(const float* __restrict__ S,
                                                   const float* __restrict__ Q) {
    constexpr int BN = 32, TM = 4, TN = 4;
    __shared__ float2 As2[8][NPTS];
    __shared__ float2 Bs2[8][BN];
    __shared__ float ns_sh[NPTS];
    __shared__ float nq_sh[BN];
    int b = blockIdx.y, cb = blockIdx.x;
    const float* Sb = S + (size_t)b * NPTS * DIM;
    const float* Qb = Q + (size_t)b * NPTS * DIM + (size_t)cb * BN * DIM;
    int tid = threadIdx.x;
    int aRow0 = tid >> 2, aK0 = (tid & 3) << 2;
    int aRow1 = aRow0 + 64;
    const float* Sr0 = Sb + (size_t)aRow0 * DIM + aK0;
    const float* Sr1 = Sb + (size_t)aRow1 * DIM + aK0;
    int bRow = tid >> 2;
    const float* Qr = Qb + (size_t)(bRow & 31) * DIM + aK0;
    int tx = tid & 7, ty = tid >> 3;
    int kk0 = aK0 >> 1;
    float sn0 = 0.f, sn1 = 0.f, qn = 0.f;

#ifdef HAS_TCGEN05
    unsigned long long acc2[TM][TN];
#pragma unroll
    for (int m = 0; m < TM; m++)
#pragma unroll
        for (int n = 0; n < TN; n++) acc2[m][n] = 0ull;

    for (int k0 = 0; k0 < DIM; k0 += 16) {
        float4 a0 = *(const float4*)(Sr0 + k0);
        float4 a1 = *(const float4*)(Sr1 + k0);
        float4 b0 = (bRow < 32) ? *(const float4*)(Qr + k0) : make_float4(0, 0, 0, 0);
        sn0 = fmaf(a0.x, a0.x, sn0); sn0 = fmaf(a0.y, a0.y, sn0);
        sn0 = fmaf(a0.z, a0.z, sn0); sn0 = fmaf(a0.w, a0.w, sn0);
        sn1 = fmaf(a1.x, a1.x, sn1); sn1 = fmaf(a1.y, a1.y, sn1);
        sn1 = fmaf(a1.z, a1.z, sn1); sn1 = fmaf(a1.w, a1.w, sn1);
        qn  = fmaf(b0.x, b0.x, qn);  qn  = fmaf(b0.y, b0.y, qn);
        qn  = fmaf(b0.z, b0.z, qn);  qn  = fmaf(b0.w, b0.w, qn);
        __syncthreads();
        As2[kk0][aRow0] = make_float2(a0.x, a0.y);
        As2[kk0 + 1][aRow0] = make_float2(a0.z, a0.w);
        As2[kk0][aRow1] = make_float2(a1.x, a1.y);
        As2[kk0 + 1][aRow1] = make_float2(a1.z, a1.w);
        if (bRow < 32) {
            Bs2[kk0][bRow] = make_float2(b0.x, b0.y);
            Bs2[kk0 + 1][bRow] = make_float2(b0.z, b0.w);
        }
        __syncthreads();
#pragma unroll
        for (int kk = 0; kk < 8; kk++) {
            unsigned long long a2[TM], b2[TN];
#pragma unroll
            for (int m = 0; m < TM; m++)
                a2[m] = *(const unsigned long long*)&As2[kk][ty * TM + m];
#pragma unroll
            for (int n = 0; n < TN; n++)
                b2[n] = *(const unsigned long long*)&Bs2[kk][tx * TN + n];
#pragma unroll
            for (int m = 0; m < TM; m++)
#pragma unroll
                for (int n = 0; n < TN; n++) fma2(acc2[m][n], a2[m], b2[n]);
        }
    }
    sn0 += __shfl_xor_sync(FULLM, sn0, 1); sn0 += __shfl_xor_sync(FULLM, sn0, 2);
    sn1 += __shfl_xor_sync(FULLM, sn1, 1); sn1 += __shfl_xor_sync(FULLM, sn1, 2);
    qn  += __shfl_xor_sync(FULLM, qn, 1);  qn  += __shfl_xor_sync(FULLM, qn, 2);
    if ((tid & 3) == 0) {
        ns_sh[aRow0] = sn0; ns_sh[aRow1] = sn1;
        if (bRow < 32) nq_sh[bRow] = qn;
    }
    __syncthreads();
#pragma unroll
    for (int m = 0; m < TM; m++) {
        int r = ty * TM + m;
        float ni = sqrtf(ns_sh[r]);
#pragma unroll
        for (int n = 0; n < TN; n++) {
            int cl = tx * TN + n;
            float nj = sqrtf(nq_sh[cl]);
            float lo = __uint_as_float((unsigned)(acc2[m][n] & 0xffffffffull));
            float hi = __uint_as_float((unsigned)(acc2[m][n] >> 32));
            d_cost[(size_t)b * NPTS * NPTS + r * NPTS + cb * BN + cl] =
                1.0f - (lo + hi) / (ni * nj);
        }
    }
#else
    float acc[TM][TN];
#pragma unroll
    for (int m = 0; m < TM; m++)
#pragma unroll
        for (int n = 0; n < TN; n++) acc[m][n] = 0.f;
    for (int k0 = 0; k0 < DIM; k0 += 16) {
        float4 a0 = *(const float4*)(Sr0 + k0);
        float4 a1 = *(const float4*)(Sr1 + k0);
        float4 b0 = (bRow < 32) ? *(const float4*)(Qr + k0) : make_float4(0, 0, 0, 0);
        sn0 = fmaf(a0.x, a0.x, sn0); sn0 = fmaf(a0.y, a0.y, sn0);
        sn0 = fmaf(a0.z, a0.z, sn0); sn0 = fmaf(a0.w, a0.w, sn0);
        sn1 = fmaf(a1.x, a1.x, sn1); sn1 = fmaf(a1.y, a1.y, sn1);
        sn1 = fmaf(a1.z, a1.z, sn1); sn1 = fmaf(a1.w, a1.w, sn1);
        qn  = fmaf(b0.x, b0.x, qn);  qn  = fmaf(b0.y, b0.y, qn);
        qn  = fmaf(b0.z, b0.z, qn);  qn  = fmaf(b0.w, b0.w, qn);
        __syncthreads();
        As2[kk0][aRow0] = make_float2(a0.x, a0.y);
        As2[kk0 + 1][aRow0] = make_float2(a0.z, a0.w);
        As2[kk0][aRow1] = make_float2(a1.x, a1.y);
        As2[kk0 + 1][aRow1] = make_float2(a1.z, a1.w);
        if (bRow < 32) {
            Bs2[kk0][bRow] = make_float2(b0.x, b0.y);
            Bs2[kk0 + 1][bRow] = make_float2(b0.z, b0.w);
        }
        __syncthreads();
#pragma unroll
        for (int kk = 0; kk < 8; kk++) {
#pragma unroll
            for (int m = 0; m < TM; m++) {
                float2 a = As2[kk][ty * TM + m];
#pragma unroll
                for (int n = 0; n < TN; n++) {
                    float2 bb = Bs2[kk][tx * TN + n];
                    acc[m][n] = fmaf(a.x, bb.x, acc[m][n]);
                    acc[m][n] = fmaf(a.y, bb.y, acc[m][n]);
                }
            }
        }
    }
    sn0 += __shfl_xor_sync(FULLM, sn0, 1); sn0 += __shfl_xor_sync(FULLM, sn0, 2);
    sn1 += __shfl_xor_sync(FULLM, sn1, 1); sn1 += __shfl_xor_sync(FULLM, sn1, 2);
    qn  += __shfl_xor_sync(FULLM, qn, 1);  qn  += __shfl_xor_sync(FULLM, qn, 2);
    if ((tid & 3) == 0) {
        ns_sh[aRow0] = sn0; ns_sh[aRow1] = sn1;
        if (bRow < 32) nq_sh[bRow] = qn;
    }
    __syncthreads();
#pragma unroll
    for (int m = 0; m < TM; m++) {
        int r = ty * TM + m;
        float ni = sqrtf(ns_sh[r]);
#pragma unroll
        for (int n = 0; n < TN; n++) {
            int cl = tx * TN + n;
            float nj = sqrtf(nq_sh[cl]);
            d_cost[(size_t)b * NPTS * NPTS + r * NPTS + cb * BN + cl] =
                1.0f - acc[m][n] / (ni * nj);
        }
    }
#endif
}

// ------------------------- merged MLP GEMM (128 x 256 tile) ------------------
// mode 0 (layer 1): X = [support; query] split by byg<32, C = d_h, relu.
// mode 1 (layer 2): X = d_h, C = byg<32 ? C0(out0) : d_tmp,
//                   resid = byg<32 ? R0 : R1, relu + resid.
// byg = blockIdx.y + yoff (lets layer 2 be split into two launches).
#define TG_SMEM (1024 + 2 * 49152)
__global__ void __launch_bounds__(256, 2)
tgemm_kernel(const float* __restrict__ A0, const float* __restrict__ A1,
             const float* __restrict__ W, float* __restrict__ C0,
             const float* __restrict__ R0, const float* __restrict__ R1,
             int N, int K, int mode, int yoff) {
    extern __shared__ char smem[];
    int tid = threadIdx.x;
    int bx = blockIdx.x, byg = blockIdx.y + yoff;
    int byl = byg & 31;
    const float* Abase;
    if (mode == 0)
        Abase = (byg < 32) ? (A0 + (size_t)byg * NPTS * K)
                           : (A1 + (size_t)(byg - 32) * NPTS * K);
    else
        Abase = d_h + (size_t)byg * NPTS * K;

#ifdef HAS_TCGEN05
    uint32_t sb = smem_u32(smem);
    int wid = tid >> 5, lane = tid & 31;

    if (wid == 0) {
        TCGEN05_ALLOC(sb, BNT);
        TCGEN05_RELINQUISH();          // release permit NOW (occ 2)
    }
    if (tid == 0) { MBARRIER_INIT(sb + 8, 1); MBARRIER_INIT(sb + 16, 1); }
    __syncthreads();
    uint32_t tmem;
    asm volatile("ld.shared.b32 %0, [%1];" : "=r"(tmem) : "r"(sb));

    int r0 = tid >> 3, kg = tid & 7;
    const float* ap0 = Abase + (size_t)r0 * K + kg * 4;
    const float* bp0 = W + (size_t)(bx * BNT + r0) * K + kg * 4;
    uint32_t soff0 = SW128((uint32_t)(r0 * 128 + kg * 16));
    size_t astep = (size_t)32 * K;

    uint64_t adesc[2] = { make_desc_sw128(sb + 1024),
                          make_desc_sw128(sb + 1024 + 49152) };
    uint64_t bdesc[2] = { make_desc_sw128(sb + 1024 + 16384),
                          make_desc_sw128(sb + 1024 + 49152 + 16384) };

    const int NCH = K / KC;
    float4 a4[4], b4[8], an[4], bn[8];
#pragma unroll
    for (int i = 0; i < 4; i++) a4[i] = *(const float4*)(ap0 + i * astep);
#pragma unroll
    for (int i = 0; i < 8; i++) b4[i] = *(const float4*)(bp0 + i * astep);
    for (int c = 0; c < NCH; c++) {
        int s = c & 1;
        uint32_t stg = 1024 + (uint32_t)s * 49152;
        if (c + 1 < NCH) {
            const float* apn = ap0 + (size_t)(c + 1) * KC;
            const float* bpn = bp0 + (size_t)(c + 1) * KC;
#pragma unroll
            for (int i = 0; i < 4; i++) an[i] = *(const float4*)(apn + i * astep);
#pragma unroll
            for (int i = 0; i < 8; i++) bn[i] = *(const float4*)(bpn + i * astep);
        }
        if (c >= 2) MBARRIER_WAIT_PARITY(sb + 8 + 8 * s, ((c >> 1) - 1) & 1);
#pragma unroll
        for (int i = 0; i < 4; i++) {
            float4 t;
            t.x = to_tf32(a4[i].x); t.y = to_tf32(a4[i].y);
            t.z = to_tf32(a4[i].z); t.w = to_tf32(a4[i].w);
            *(float4*)(smem + stg + soff0 + i * 4096u) = t;
        }
#pragma unroll
        for (int i = 0; i < 8; i++) {
            float4 t;
            t.x = to_tf32(b4[i].x); t.y = to_tf32(b4[i].y);
            t.z = to_tf32(b4[i].z); t.w = to_tf32(b4[i].w);
            *(float4*)(smem + stg + 16384 + soff0 + i * 4096u) = t;
        }
        __syncthreads();
        if (tid == 0) {
            asm volatile("fence.proxy.async.shared::cta;" ::: "memory");
#pragma unroll
            for (int k = 0; k < 4; k++)
                mma_tf32_ss(tmem, adesc[s] + k * 2, bdesc[s] + k * 2, IDESC_TF32, (c | k) != 0);
            TCGEN05_COMMIT(sb + 8 + 8 * s);
        }
#pragma unroll
        for (int i = 0; i < 4; i++) a4[i] = an[i];
#pragma unroll
        for (int i = 0; i < 8; i++) b4[i] = bn[i];
    }
    MBARRIER_WAIT_PARITY(sb + 8 + 8 * ((NCH - 1) & 1), ((NCH - 1) >> 1) & 1);
    TCGEN05_FENCE_AFTER();

    float* St = (float*)(smem + 1024);
    int wrow = tid >> 1, wc0 = (tid & 1) * 8;
    float* Cb; const float* rres = nullptr;
    if (mode == 0) {
        Cb = d_h + (size_t)(byg * NPTS + wrow) * N;
    } else {
        size_t lr = (size_t)(byl * NPTS + wrow);
        Cb = ((byg < 32) ? C0 : d_tmp) + lr * N;
        rres = ((byg < 32) ? R0 : R1) + lr * N;
    }
    for (int g = 0; g < BNT / 16; g++) {
        if (tid < 128) {
            uint32_t r16[16];
            TCGEN05_LD_32X32B_X16(r16, tmem + g * 16);
            TCGEN05_WAIT_LD();
            int row = wid * 32 + lane;
#pragma unroll
            for (int cc = 0; cc < 16; cc++)
                St[row * 17 + cc] = __uint_as_float(r16[cc]);
        }
        __syncthreads();
        {
            int col = bx * BNT + g * 16 + wc0;
            float o[8];
#pragma unroll
            for (int cc = 0; cc < 8; cc++) {
                float f = fmaxf(St[wrow * 17 + wc0 + cc], 0.f);
                if (mode == 1) f += rres[col + cc];
                o[cc] = f;
            }
            *(float4*)(Cb + col)     = make_float4(o[0], o[1], o[2], o[3]);
            *(float4*)(Cb + col + 4) = make_float4(o[4], o[5], o[6], o[7]);
        }
        __syncthreads();
    }
    TCGEN05_FENCE_BEFORE();
    if (wid == 0) TCGEN05_DEALLOC(tmem, BNT);

#else  // ---------------- FFMA fallback (generic PTX pass; never runs) -------
    constexpr int BK = 16, TM = 8, TN = 8;
    float* As = (float*)smem;
    float* Bs = (float*)(smem + 8192);
    int aRow0 = tid >> 2, aK0 = (tid & 3) << 2;
    int aRow1 = aRow0 + 64;
    const float* Xr0 = Abase + (size_t)aRow0 * K + aK0;
    const float* Xr1 = Abase + (size_t)aRow1 * K + aK0;
    int tx = tid & 15, ty = tid >> 4;
    for (int nh = 0; nh < BNT / 128; nh++) {
        int colbase = bx * BNT + nh * 128;
        const float* Wr0 = W + (size_t)(colbase + aRow0) * K + aK0;
        const float* Wr1 = W + (size_t)(colbase + aRow1) * K + aK0;
        float acc[TM][TN];
#pragma unroll
        for (int m = 0; m < TM; m++)
#pragma unroll
            for (int n = 0; n < TN; n++) acc[m][n] = 0.f;
        for (int k0 = 0; k0 < K; k0 += BK) {
            float4 a0 = *(const float4*)(Xr0 + k0);
            float4 a1 = *(const float4*)(Xr1 + k0);
            float4 b0 = *(const float4*)(Wr0 + k0);
            float4 b1 = *(const float4*)(Wr1 + k0);
            __syncthreads();
            As[(aK0 + 0) * 128 + aRow0] = a0.x; As[(aK0 + 1) * 128 + aRow0] = a0.y;
            As[(aK0 + 2) * 128 + aRow0] = a0.z; As[(aK0 + 3) * 128 + aRow0] = a0.w;
            As[(aK0 + 0) * 128 + aRow1] = a1.x; As[(aK0 + 1) * 128 + aRow1] = a1.y;
            As[(aK0 + 2) * 128 + aRow1] = a1.z; As[(aK0 + 3) * 128 + aRow1] = a1.w;
            Bs[(aK0 + 0) * 128 + aRow0] = b0.x; Bs[(aK0 + 1) * 128 + aRow0] = b0.y;
            Bs[(aK0 + 2) * 128 + aRow0] = b0.z; Bs[(aK0 + 3) * 128 + aRow0] = b0.w;
            Bs[(aK0 + 0) * 128 + aRow1] = b1.x; Bs[(aK0 + 1) * 128 + aRow1] = b1.y;
            Bs[(aK0 + 2) * 128 + aRow1] = b1.z; Bs[(aK0 + 3) * 128 + aRow1] = b1.w;
            __syncthreads();
#pragma unroll
            for (int k = 0; k < BK; k++) {
#pragma unroll
                for (int m = 0; m < TM; m++) {
                    float a = As[k * 128 + ty * TM + m];
#pragma unroll
                    for (int n = 0; n < TN; n++)
                        acc[m][n] = fmaf(a, Bs[k * 128 + tx * TN + n], acc[m][n]);
                }
            }
        }
        int lr0 = (mode == 0) ? (byg * NPTS + ty * TM) : (byl * NPTS + ty * TM);
        int col0 = colbase + tx * TN;
        float* Csel = (mode == 0) ? d_h : ((byg < 32) ? C0 : d_tmp);
        const float* Rsel = (mode == 1) ? ((byg < 32) ? R0 : R1) : nullptr;
#pragma unroll
        for (int m = 0; m < TM; m++) {
            int gr = lr0 + m;
            const float* rr = Rsel ? (Rsel + (size_t)gr * N) : nullptr;
#pragma unroll
            for (int n = 0; n < TN; n++) {
                float vv = fmaxf(acc[m][n], 0.f);
                if (rr) vv += rr[col0 + n];
                Csel[(size_t)gr * N + col0 + n] = vv;
            }
        }
        __syncthreads();
    }
#endif
}

// ------------------- JV Hungarian (colred + ARR + Dijkstra) ------------------
__device__ __forceinline__ unsigned fkey(float f) {
    unsigned u = __float_as_uint(f);
    return (u & 0x80000000u) ? ~u : (u | 0x80000000u);
}
__device__ __forceinline__ float fuk(unsigned k) {
    k = (k & 0x80000000u) ? (k & 0x7fffffffu) : ~k;
    return __uint_as_float(k);
}

__global__ void lap_kernel() {
    extern __shared__ float csh[];            // [128][128] cost, 64KB
    __shared__ float u_sh[NPTS];
    __shared__ int   roc_sh[NPTS];            // row of col (-1 free)
    __shared__ int   cor_sh[NPTS];            // col of row (-1 free)
    __shared__ int   way_sh[NPTS];
    __shared__ int   im_sh[NPTS];
    __shared__ int   fl_sh[192];              // ARR worklist
    __shared__ int   brd[3];
    __shared__ float brdf[1];
    int b = blockIdx.x, lane = threadIdx.x;

    const float4* src = (const float4*)(d_cost + (size_t)b * NPTS * NPTS);
    float4* dst = (float4*)csh;
    for (int i = lane; i < NPTS * NPTS / 4; i += 32) dst[i] = src[i];
    for (int r = lane; r < NPTS; r += 32) {
        u_sh[r] = 0.f; cor_sh[r] = -1; roc_sh[r] = -1;
    }
    __syncwarp();

    // ---- phase 1: column reduction + greedy assign ----
    float v[4] = {INFINITY, INFINITY, INFINITY, INFINITY};
    int im[4] = {0, 0, 0, 0};
    for (int i = 0; i < NPTS; i++) {
        float4 c4 = *(const float4*)(csh + i * NPTS + 4 * lane);
        float cc[4] = {c4.x, c4.y, c4.z, c4.w};
#pragma unroll
        for (int t = 0; t < 4; t++)
            if (cc[t] < v[t]) { v[t] = cc[t]; im[t] = i; }
    }
#pragma unroll
    for (int t = 0; t < 4; t++) im_sh[4 * lane + t] = im[t];
    __syncwarp();
    if (lane == 0) {
        for (int j = 0; j < NPTS; j++) {
            int i = im_sh[j];
            if (cor_sh[i] < 0) { cor_sh[i] = j; roc_sh[j] = i; }
        }
    }
    __syncwarp();

    // ---- phase 2: augmenting row reduction (lapjv ARR, step-capped) ----
    {
        int k = 0, nf = 0, steps = 0;        // lane0-authoritative
        if (lane == 0) {
            for (int r = 0; r < NPTS; r++) if (cor_sh[r] < 0) fl_sh[nf++] = r;
        }
        while (true) {
            if (lane == 0) brd[0] = (k < nf && steps < 3 * NPTS) ? fl_sh[k] : -1;
            __syncwarp();
            int i = brd[0];
            if (i < 0) break;
            steps++;
            // warp scan of row i: (min1, col1, min2, col2) of c[i][j]-v[j]
            float4 c4 = *(const float4*)(csh + i * NPTS + 4 * lane);
            float rr[4] = {c4.x - v[0], c4.y - v[1], c4.z - v[2], c4.w - v[3]};
            float m1 = rr[0], m2 = INFINITY;
            int j1l = 4 * lane, j2l = 4 * lane;
#pragma unroll
            for (int t = 1; t < 4; t++) {
                int j = 4 * lane + t;
                if (rr[t] < m1) { m2 = m1; j2l = j1l; m1 = rr[t]; j1l = j; }
                else if (rr[t] < m2) { m2 = rr[t]; j2l = j; }
            }
            for (int off = 16; off; off >>= 1) {
                float om1 = __shfl_down_sync(FULLM, m1, off);
                float om2 = __shfl_down_sync(FULLM, m2, off);
                int oj1 = __shfl_down_sync(FULLM, j1l, off);
                int oj2 = __shfl_down_sync(FULLM, j2l, off);
                if (om1 < m1) {
                    if (m1 < om2) { m2 = m1; j2l = j1l; }
                    else { m2 = om2; j2l = oj2; }
                    m1 = om1; j1l = oj1;
                } else if (om1 < m2) { m2 = om1; j2l = oj1; }
            }
            if (lane == 0) {
                float u1 = m1, u2 = m2;
                int j1 = j1l, dec = -1;
                if (u1 < u2) dec = j1;
                else if (roc_sh[j1] >= 0) j1 = j2l;
                int i0 = roc_sh[j1];
                if (i0 >= 0) {
                    cor_sh[i0] = -1;
                    if (u1 < u2) fl_sh[k] = i0;          // reprocess in place
                    else { if (nf < 192) fl_sh[nf++] = i0; k++; }
                } else k++;
                roc_sh[j1] = i; cor_sh[i] = j1;
                brd[1] = dec; brdf[0] = u2 - u1;
            }
            __syncwarp();
            int jd = brd[1];
            if (jd >= 0 && lane == (jd >> 2)) v[jd & 3] -= brdf[0];
        }
    }
    __syncwarp();
    // exact duals for matched rows: u[i] = c[i][cor[i]] - v[cor[i]]
#pragma unroll
    for (int t = 0; t < 4; t++) {
        int j = 4 * lane + t;
        int i = roc_sh[j];
        if (i >= 0) u_sh[i] = csh[i * NPTS + j] - v[t];
    }
    __syncwarp();

    // ---- phase 3: Dijkstra augmentation for remaining free rows ----
    int roc_r[4];
#pragma unroll
    for (int t = 0; t < 4; t++) roc_r[t] = roc_sh[4 * lane + t];

    for (int i = 0; i < NPTS; i++) {
        if (cor_sh[i] >= 0) continue;
        float dist[4] = {INFINITY, INFINITY, INFINITY, INFINITY};
        int usedm = 0;
        int i0 = i, j0 = -1, jfin = -1;
        float D = 0.f, ui0 = u_sh[i0];
        for (int it = 0; it < NPTS + 2; it++) {
            float4 c4 = *(const float4*)(csh + i0 * NPTS + 4 * lane);
            float cc[4] = {c4.x, c4.y, c4.z, c4.w};
            float best = INFINITY; int jb = 0x7ffffffc;
#pragma unroll
            for (int t = 0; t < 4; t++) {
                if (!((usedm >> t) & 1)) {
                    float nd = D + cc[t] - ui0 - v[t];
                    if (nd < dist[t]) { dist[t] = nd; way_sh[4 * lane + t] = j0; }
                    if (dist[t] < best) { best = dist[t]; jb = 4 * lane + t; }
                }
            }
            unsigned key = fkey(best);
            unsigned kmin = __reduce_min_sync(FULLM, key);
            unsigned bal = __ballot_sync(FULLM, key == kmin);
            int srcl = __ffs(bal) - 1;
            int ir = roc_r[jb & 3];               // owner's matched row for jb
            int j1 = __shfl_sync(FULLM, jb, srcl);
            int i1 = __shfl_sync(FULLM, ir, srcl);
            D = fuk(kmin);
            if (i1 < 0) { jfin = j1; break; }
            { int ol = j1 >> 2, ot = j1 & 3; if (lane == ol) usedm |= 1 << ot; }
            i0 = i1; ui0 = u_sh[i0]; j0 = j1;
        }
        __syncwarp();
#pragma unroll
        for (int t = 0; t < 4; t++) {
            if ((usedm >> t) & 1) {
                float dd = D - dist[t];
                v[t] -= dd;
                u_sh[roc_r[t]] += dd;
            }
        }
        if (lane == 0) u_sh[i] += D;
        __syncwarp();
        if (lane == 0) {
            int j = jfin;
            while (way_sh[j] >= 0) { int jp = way_sh[j]; roc_sh[j] = roc_sh[jp]; j = jp; }
            roc_sh[j] = i;
        }
        __syncwarp();
#pragma unroll
        for (int t = 0; t < 4; t++) roc_r[t] = roc_sh[4 * lane + t];
    }
    for (int j = lane; j < NPTS; j += 32)
        d_perm[b * NPTS + roc_sh[j]] = b * NPTS + j;
}

// --------------------------- out1 permutation gather ------------------------
__global__ void gather_kernel(float* __restrict__ out1) {
    int g = blockIdx.x;
    int src = d_perm[g];
    const float4* s = (const float4*)(d_tmp + (size_t)src * DIM);
    float4* d = (float4*)(out1 + (size_t)g * DIM);
    for (int k = threadIdx.x; k < DIM / 4; k += 256) d[k] = s[k];
}

// ------------------------------ launch --------------------------------------
static cudaStream_t g_s2 = nullptr;
static cudaEvent_t g_evF = nullptr, g_evJ = nullptr, g_evJ2 = nullptr;

extern "C" void kernel_launch(void* const* d_in, const int* in_sizes, int n_in,
                              void* d_out, int out_size) {
    const float* support = (const float*)d_in[0];
    const float* query   = (const float*)d_in[1];
    const float* W1      = (const float*)d_in[2];   // [1024, 2048]
    const float* W2      = (const float*)d_in[3];   // [2048, 1024]
    float* out0 = (float*)d_out;
    float* out1 = out0 + (size_t)MROWS * DIM;

    if (!g_s2) {   // one-time resource creation (first call is uncaptured)
        int lo, hi;
        cudaDeviceGetStreamPriorityRange(&lo, &hi);
        cudaStreamCreateWithPriority(&g_s2, cudaStreamNonBlocking, lo);  // low prio
        cudaEventCreateWithFlags(&g_evF, cudaEventDisableTiming);
        cudaEventCreateWithFlags(&g_evJ, cudaEventDisableTiming);
        cudaEventCreateWithFlags(&g_evJ2, cudaEventDisableTiming);
        cudaFuncSetAttribute(lap_kernel, cudaFuncAttributeMaxDynamicSharedMemorySize, 65536);
        cudaFuncSetAttribute(tgemm_kernel, cudaFuncAttributeMaxDynamicSharedMemorySize, TG_SMEM);
    }

    // fork: GEMM chain (independent of matching) runs on s2 concurrently
    cudaEventRecord(g_evF, 0);
    cudaStreamWaitEvent(g_s2, g_evF, 0);

    // stream 0: matching path (norms fused into cost)
    cost_kernel<<<dim3(4, BATCH), 256>>>(support, query);
    lap_kernel<<<BATCH, 32, 65536>>>();

    // stream s2: MLP. Layer 1 merged; layer 2 split so the query half (feeding
    // the gather) finishes first and the support half overlaps the gather.
    tgemm_kernel<<<dim3(HID / BNT, 2 * BATCH), 256, TG_SMEM, g_s2>>>(
        support, query, W1, nullptr, nullptr, nullptr, HID, DIM, 0, 0);
    tgemm_kernel<<<dim3(DIM / BNT, BATCH), 256, TG_SMEM, g_s2>>>(
        nullptr, nullptr, W2, out0, support, query, DIM, HID, 1, 32);  // query -> d_tmp
    cudaEventRecord(g_evJ, g_s2);                                      // gather dep
    tgemm_kernel<<<dim3(DIM / BNT, BATCH), 256, TG_SMEM, g_s2>>>(
        nullptr, nullptr, W2, out0, support, query, DIM, HID, 1, 0);   // support -> out0
    cudaEventRecord(g_evJ2, g_s2);                                     // branch tail

    // join query-half + lap, launch gather; then join the s2 tail so the
    // capture graph has no unjoined forked work.
    cudaStreamWaitEvent(0, g_evJ, 0);
    gather_kernel<<<MROWS, 256>>>(out1);
    cudaStreamWaitEvent(0, g_evJ2, 0);
}

// round 14
// speedup vs baseline: 1.0059x; 1.0059x over previous
#include <cuda_runtime.h>
#include <math.h>
#include <stdint.h>

#define BATCH 32
#define NPTS  128
#define DIM   2048
#define HID   1024
#define MROWS (BATCH * NPTS)   // 4096
#define KC    32               // K floats per smem chunk (= 128B SW128 atom row)
#define BNT   256              // GEMM N tile
#define FULLM 0xffffffffu

// tcgen05 / f32x2 only exist in the sm_103a (arch-specific) compilation pass.
#ifdef __CUDA_ARCH_FEAT_SM103_ALL
#define HAS_TCGEN05 1
#endif

// ------------------------------ scratch ------------------------------------
__device__ float d_cost[BATCH * NPTS * NPTS];
__device__ int   d_perm[MROWS];                 // d_perm[g] = global src row of out1 row g
__device__ float d_h[2u * MROWS * HID];         // hidden acts: rows 0..4095 support, 4096..8191 query
__device__ float d_tmp[(size_t)MROWS * DIM];    // query + mlp(query), unpermuted

// ------------------------------ PTX helpers ---------------------------------
__device__ __forceinline__ uint32_t smem_u32(const void* p) {
    uint32_t a;
    asm("{ .reg .u64 t; cvta.to.shared.u64 t, %1; cvt.u32.u64 %0, t; }"
        : "=r"(a) : "l"(p));
    return a;
}
#define SW128(o) ((o) ^ (((o) >> 3) & 0x70))

#ifdef HAS_TCGEN05
__device__ __forceinline__ float to_tf32(float x) {
    float r; asm("cvt.rna.tf32.f32 %0, %1;" : "=f"(r) : "f"(x)); return r;
}
#define TCGEN05_ALLOC(smem_addr, nCols) \
    asm volatile("tcgen05.alloc.cta_group::1.sync.aligned.shared::cta.b32 [%0], %1;" \
        :: "r"((uint32_t)(smem_addr)), "r"((uint32_t)(nCols)) : "memory")
#define TCGEN05_DEALLOC(tmem_addr, nCols) \
    asm volatile("tcgen05.dealloc.cta_group::1.sync.aligned.b32 %0, %1;" \
        :: "r"(tmem_addr), "r"((uint32_t)(nCols)))
#define TCGEN05_RELINQUISH() \
    asm volatile("tcgen05.relinquish_alloc_permit.cta_group::1.sync.aligned;")
#define TCGEN05_COMMIT(mbar) \
    asm volatile("tcgen05.commit.cta_group::1.mbarrier::arrive::one.shared::cluster.b64 [%0];" \
        :: "r"((uint32_t)(mbar)) : "memory")
#define TCGEN05_FENCE_AFTER() \
    asm volatile("tcgen05.fence::after_thread_sync;" ::: "memory")
#define TCGEN05_FENCE_BEFORE() \
    asm volatile("tcgen05.fence::before_thread_sync;" ::: "memory")
#define TCGEN05_WAIT_LD() \
    asm volatile("tcgen05.wait::ld.sync.aligned;" ::: "memory")
#define TCGEN05_LD_32X32B_X16(r, tmem_addr) \
    asm volatile("tcgen05.ld.sync.aligned.32x32b.x16.b32 " \
        "{%0, %1, %2, %3, %4, %5, %6, %7, %8, %9, %10, %11, %12, %13, %14, %15}, [%16];" \
        : "=r"((r)[0]), "=r"((r)[1]), "=r"((r)[2]), "=r"((r)[3]), \
          "=r"((r)[4]), "=r"((r)[5]), "=r"((r)[6]), "=r"((r)[7]), \
          "=r"((r)[8]), "=r"((r)[9]), "=r"((r)[10]), "=r"((r)[11]), \
          "=r"((r)[12]), "=r"((r)[13]), "=r"((r)[14]), "=r"((r)[15]) \
        : "r"(tmem_addr))
#define MBARRIER_INIT(mbar, count) \
    asm volatile("mbarrier.init.shared.b64 [%0], %1;" \
        :: "r"((uint32_t)(mbar)), "r"((uint32_t)(count)) : "memory")
#define MBARRIER_WAIT_PARITY(mbar, parity) do { \
    uint32_t _m = (uint32_t)(mbar); uint32_t _p = (uint32_t)(parity); uint32_t _d; \
    asm volatile("{\n\t.reg .pred p;\n\t" \
        "mbarrier.try_wait.parity.acquire.cta.shared::cta.b64 p, [%1], %2;\n\t" \
        "selp.b32 %0, 1, 0, p;\n\t}" : "=r"(_d) : "r"(_m), "r"(_p) : "memory"); \
    if (!_d) { \
        asm volatile("{\n\t.reg .pred P1;\n\t" \
            "WL_%=:\n\t" \
            "mbarrier.try_wait.parity.acquire.cta.shared::cta.b64 P1, [%0], %1, 0x989680;\n\t" \
            "@P1 bra.uni WD_%=;\n\t" \
            "bra.uni WL_%=;\n\t" \
            "WD_%=:\n\t}" :: "r"(_m), "r"(_p) : "memory"); \
    } \
} while (0)

__device__ __forceinline__ void mma_tf32_ss(uint32_t d, uint64_t ad, uint64_t bd,
                                            uint32_t idesc, int acc) {
    asm volatile("{\n\t.reg .pred p;\n\t"
        "setp.ne.u32 p, %4, 0;\n\t"
        "tcgen05.mma.cta_group::1.kind::tf32 [%0], %1, %2, %3, {%5, %5, %5, %5}, p;\n\t"
        "}" :: "r"(d), "l"(ad), "l"(bd), "r"(idesc), "r"(acc), "r"(0u) : "memory");
}
// idesc: c=F32(1<<4), a=TF32(2<<7), b=TF32(2<<10), N=256(32<<17), M=128(8<<24)
#define IDESC_TF32 ((8u << 24) | ((BNT / 8u) << 17) | (2u << 10) | (2u << 7) | (1u << 4))

__device__ __forceinline__ uint64_t make_desc_sw128(uint32_t addr) {
    return ((uint64_t)2 << 61) | ((uint64_t)1 << 46) | ((uint64_t)64 << 32)
         | ((uint64_t)1 << 16) | ((addr >> 4) & 0x3FFF);
}

__device__ __forceinline__ void fma2(unsigned long long& d,
                                     unsigned long long a, unsigned long long b) {
    asm("fma.rn.f32x2 %0, %1, %2, %0;" : "+l"(d) : "l"(a), "l"(b));
}
#endif // HAS_TCGEN05

// ------------------------- cost (fp32) + fused norms -------------------------
__global__ void __launch_bounds__(256) cost_kernel(const float* __restrict__ S,
                                                   const float* __restrict__ Q) {
    constexpr int BN = 32, TM = 4, TN = 4;
    __shared__ float2 As2[8][NPTS];
    __shared__ float2 Bs2[8][BN];
    __shared__ float ns_sh[NPTS];
    __shared__ float nq_sh[BN];
    int b = blockIdx.y, cb = blockIdx.x;
    const float* Sb = S + (size_t)b * NPTS * DIM;
    const float* Qb = Q + (size_t)b * NPTS * DIM + (size_t)cb * BN * DIM;
    int tid = threadIdx.x;
    int aRow0 = tid >> 2, aK0 = (tid & 3) << 2;
    int aRow1 = aRow0 + 64;
    const float* Sr0 = Sb + (size_t)aRow0 * DIM + aK0;
    const float* Sr1 = Sb + (size_t)aRow1 * DIM + aK0;
    int bRow = tid >> 2;
    const float* Qr = Qb + (size_t)(bRow & 31) * DIM + aK0;
    int tx = tid & 7, ty = tid >> 3;
    int kk0 = aK0 >> 1;
    float sn0 = 0.f, sn1 = 0.f, qn = 0.f;

#ifdef HAS_TCGEN05
    unsigned long long acc2[TM][TN];
#pragma unroll
    for (int m = 0; m < TM; m++)
#pragma unroll
        for (int n = 0; n < TN; n++) acc2[m][n] = 0ull;

    for (int k0 = 0; k0 < DIM; k0 += 16) {
        float4 a0 = *(const float4*)(Sr0 + k0);
        float4 a1 = *(const float4*)(Sr1 + k0);
        float4 b0 = (bRow < 32) ? *(const float4*)(Qr + k0) : make_float4(0, 0, 0, 0);
        sn0 = fmaf(a0.x, a0.x, sn0); sn0 = fmaf(a0.y, a0.y, sn0);
        sn0 = fmaf(a0.z, a0.z, sn0); sn0 = fmaf(a0.w, a0.w, sn0);
        sn1 = fmaf(a1.x, a1.x, sn1); sn1 = fmaf(a1.y, a1.y, sn1);
        sn1 = fmaf(a1.z, a1.z, sn1); sn1 = fmaf(a1.w, a1.w, sn1);
        qn  = fmaf(b0.x, b0.x, qn);  qn  = fmaf(b0.y, b0.y, qn);
        qn  = fmaf(b0.z, b0.z, qn);  qn  = fmaf(b0.w, b0.w, qn);
        __syncthreads();
        As2[kk0][aRow0] = make_float2(a0.x, a0.y);
        As2[kk0 + 1][aRow0] = make_float2(a0.z, a0.w);
        As2[kk0][aRow1] = make_float2(a1.x, a1.y);
        As2[kk0 + 1][aRow1] = make_float2(a1.z, a1.w);
        if (bRow < 32) {
            Bs2[kk0][bRow] = make_float2(b0.x, b0.y);
            Bs2[kk0 + 1][bRow] = make_float2(b0.z, b0.w);
        }
        __syncthreads();
#pragma unroll
        for (int kk = 0; kk < 8; kk++) {
            unsigned long long a2[TM], b2[TN];
#pragma unroll
            for (int m = 0; m < TM; m++)
                a2[m] = *(const unsigned long long*)&As2[kk][ty * TM + m];
#pragma unroll
            for (int n = 0; n < TN; n++)
                b2[n] = *(const unsigned long long*)&Bs2[kk][tx * TN + n];
#pragma unroll
            for (int m = 0; m < TM; m++)
#pragma unroll
                for (int n = 0; n < TN; n++) fma2(acc2[m][n], a2[m], b2[n]);
        }
    }
    sn0 += __shfl_xor_sync(FULLM, sn0, 1); sn0 += __shfl_xor_sync(FULLM, sn0, 2);
    sn1 += __shfl_xor_sync(FULLM, sn1, 1); sn1 += __shfl_xor_sync(FULLM, sn1, 2);
    qn  += __shfl_xor_sync(FULLM, qn, 1);  qn  += __shfl_xor_sync(FULLM, qn, 2);
    if ((tid & 3) == 0) {
        ns_sh[aRow0] = sn0; ns_sh[aRow1] = sn1;
        if (bRow < 32) nq_sh[bRow] = qn;
    }
    __syncthreads();
#pragma unroll
    for (int m = 0; m < TM; m++) {
        int r = ty * TM + m;
        float ni = sqrtf(ns_sh[r]);
#pragma unroll
        for (int n = 0; n < TN; n++) {
            int cl = tx * TN + n;
            float nj = sqrtf(nq_sh[cl]);
            float lo = __uint_as_float((unsigned)(acc2[m][n] & 0xffffffffull));
            float hi = __uint_as_float((unsigned)(acc2[m][n] >> 32));
            d_cost[(size_t)b * NPTS * NPTS + r * NPTS + cb * BN + cl] =
                1.0f - (lo + hi) / (ni * nj);
        }
    }
#else
    float acc[TM][TN];
#pragma unroll
    for (int m = 0; m < TM; m++)
#pragma unroll
        for (int n = 0; n < TN; n++) acc[m][n] = 0.f;
    for (int k0 = 0; k0 < DIM; k0 += 16) {
        float4 a0 = *(const float4*)(Sr0 + k0);
        float4 a1 = *(const float4*)(Sr1 + k0);
        float4 b0 = (bRow < 32) ? *(const float4*)(Qr + k0) : make_float4(0, 0, 0, 0);
        sn0 = fmaf(a0.x, a0.x, sn0); sn0 = fmaf(a0.y, a0.y, sn0);
        sn0 = fmaf(a0.z, a0.z, sn0); sn0 = fmaf(a0.w, a0.w, sn0);
        sn1 = fmaf(a1.x, a1.x, sn1); sn1 = fmaf(a1.y, a1.y, sn1);
        sn1 = fmaf(a1.z, a1.z, sn1); sn1 = fmaf(a1.w, a1.w, sn1);
        qn  = fmaf(b0.x, b0.x, qn);  qn  = fmaf(b0.y, b0.y, qn);
        qn  = fmaf(b0.z, b0.z, qn);  qn  = fmaf(b0.w, b0.w, qn);
        __syncthreads();
        As2[kk0][aRow0] = make_float2(a0.x, a0.y);
        As2[kk0 + 1][aRow0] = make_float2(a0.z, a0.w);
        As2[kk0][aRow1] = make_float2(a1.x, a1.y);
        As2[kk0 + 1][aRow1] = make_float2(a1.z, a1.w);
        if (bRow < 32) {
            Bs2[kk0][bRow] = make_float2(b0.x, b0.y);
            Bs2[kk0 + 1][bRow] = make_float2(b0.z, b0.w);
        }
        __syncthreads();
#pragma unroll
        for (int kk = 0; kk < 8; kk++) {
#pragma unroll
            for (int m = 0; m < TM; m++) {
                float2 a = As2[kk][ty * TM + m];
#pragma unroll
                for (int n = 0; n < TN; n++) {
                    float2 bb = Bs2[kk][tx * TN + n];
                    acc[m][n] = fmaf(a.x, bb.x, acc[m][n]);
                    acc[m][n] = fmaf(a.y, bb.y, acc[m][n]);
                }
            }
        }
    }
    sn0 += __shfl_xor_sync(FULLM, sn0, 1); sn0 += __shfl_xor_sync(FULLM, sn0, 2);
    sn1 += __shfl_xor_sync(FULLM, sn1, 1); sn1 += __shfl_xor_sync(FULLM, sn1, 2);
    qn  += __shfl_xor_sync(FULLM, qn, 1);  qn  += __shfl_xor_sync(FULLM, qn, 2);
    if ((tid & 3) == 0) {
        ns_sh[aRow0] = sn0; ns_sh[aRow1] = sn1;
        if (bRow < 32) nq_sh[bRow] = qn;
    }
    __syncthreads();
#pragma unroll
    for (int m = 0; m < TM; m++) {
        int r = ty * TM + m;
        float ni = sqrtf(ns_sh[r]);
#pragma unroll
        for (int n = 0; n < TN; n++) {
            int cl = tx * TN + n;
            float nj = sqrtf(nq_sh[cl]);
            d_cost[(size_t)b * NPTS * NPTS + r * NPTS + cb * BN + cl] =
                1.0f - acc[m][n] / (ni * nj);
        }
    }
#endif
}

// ------------------------- merged MLP GEMM (128 x 256 tile) ------------------
// mode 0 (layer 1): X = [support; query] split by byg<32, C = d_h, relu.
// mode 1 (layer 2): X = d_h, C = byg<32 ? C0(out0) : d_tmp,
//                   resid = byg<32 ? R0 : R1, relu + resid.
#define TG_SMEM (1024 + 2 * 49152)
__global__ void __launch_bounds__(256, 2)
tgemm_kernel(const float* __restrict__ A0, const float* __restrict__ A1,
             const float* __restrict__ W, float* __restrict__ C0,
             const float* __restrict__ R0, const float* __restrict__ R1,
             int N, int K, int mode, int yoff) {
    extern __shared__ char smem[];
    int tid = threadIdx.x;
    int bx = blockIdx.x, byg = blockIdx.y + yoff;
    int byl = byg & 31;
    const float* Abase;
    if (mode == 0)
        Abase = (byg < 32) ? (A0 + (size_t)byg * NPTS * K)
                           : (A1 + (size_t)(byg - 32) * NPTS * K);
    else
        Abase = d_h + (size_t)byg * NPTS * K;

#ifdef HAS_TCGEN05
    uint32_t sb = smem_u32(smem);
    int wid = tid >> 5, lane = tid & 31;

    if (wid == 0) {
        TCGEN05_ALLOC(sb, BNT);
        TCGEN05_RELINQUISH();          // release permit NOW (occ 2)
    }
    if (tid == 0) { MBARRIER_INIT(sb + 8, 1); MBARRIER_INIT(sb + 16, 1); }
    __syncthreads();
    uint32_t tmem;
    asm volatile("ld.shared.b32 %0, [%1];" : "=r"(tmem) : "r"(sb));

    int r0 = tid >> 3, kg = tid & 7;
    const float* ap0 = Abase + (size_t)r0 * K + kg * 4;
    const float* bp0 = W + (size_t)(bx * BNT + r0) * K + kg * 4;
    uint32_t soff0 = SW128((uint32_t)(r0 * 128 + kg * 16));
    size_t astep = (size_t)32 * K;

    uint64_t adesc[2] = { make_desc_sw128(sb + 1024),
                          make_desc_sw128(sb + 1024 + 49152) };
    uint64_t bdesc[2] = { make_desc_sw128(sb + 1024 + 16384),
                          make_desc_sw128(sb + 1024 + 49152 + 16384) };

    const int NCH = K / KC;
    float4 a4[4], b4[8], an[4], bn[8];
#pragma unroll
    for (int i = 0; i < 4; i++) a4[i] = *(const float4*)(ap0 + i * astep);
#pragma unroll
    for (int i = 0; i < 8; i++) b4[i] = *(const float4*)(bp0 + i * astep);
    for (int c = 0; c < NCH; c++) {
        int s = c & 1;
        uint32_t stg = 1024 + (uint32_t)s * 49152;
        if (c + 1 < NCH) {
            const float* apn = ap0 + (size_t)(c + 1) * KC;
            const float* bpn = bp0 + (size_t)(c + 1) * KC;
#pragma unroll
            for (int i = 0; i < 4; i++) an[i] = *(const float4*)(apn + i * astep);
#pragma unroll
            for (int i = 0; i < 8; i++) bn[i] = *(const float4*)(bpn + i * astep);
        }
        if (c >= 2) MBARRIER_WAIT_PARITY(sb + 8 + 8 * s, ((c >> 1) - 1) & 1);
#pragma unroll
        for (int i = 0; i < 4; i++) {
            float4 t;
            t.x = to_tf32(a4[i].x); t.y = to_tf32(a4[i].y);
            t.z = to_tf32(a4[i].z); t.w = to_tf32(a4[i].w);
            *(float4*)(smem + stg + soff0 + i * 4096u) = t;
        }
#pragma unroll
        for (int i = 0; i < 8; i++) {
            float4 t;
            t.x = to_tf32(b4[i].x); t.y = to_tf32(b4[i].y);
            t.z = to_tf32(b4[i].z); t.w = to_tf32(b4[i].w);
            *(float4*)(smem + stg + 16384 + soff0 + i * 4096u) = t;
        }
        __syncthreads();
        if (tid == 0) {
            asm volatile("fence.proxy.async.shared::cta;" ::: "memory");
#pragma unroll
            for (int k = 0; k < 4; k++)
                mma_tf32_ss(tmem, adesc[s] + k * 2, bdesc[s] + k * 2, IDESC_TF32, (c | k) != 0);
            TCGEN05_COMMIT(sb + 8 + 8 * s);
        }
#pragma unroll
        for (int i = 0; i < 4; i++) a4[i] = an[i];
#pragma unroll
        for (int i = 0; i < 8; i++) b4[i] = bn[i];
    }
    MBARRIER_WAIT_PARITY(sb + 8 + 8 * ((NCH - 1) & 1), ((NCH - 1) >> 1) & 1);
    TCGEN05_FENCE_AFTER();

    float* St = (float*)(smem + 1024);
    int wrow = tid >> 1, wc0 = (tid & 1) * 8;
    float* Cb; const float* rres = nullptr;
    if (mode == 0) {
        Cb = d_h + (size_t)(byg * NPTS + wrow) * N;
    } else {
        size_t lr = (size_t)(byl * NPTS + wrow);
        Cb = ((byg < 32) ? C0 : d_tmp) + lr * N;
        rres = ((byg < 32) ? R0 : R1) + lr * N;
    }
    for (int g = 0; g < BNT / 16; g++) {
        if (tid < 128) {
            uint32_t r16[16];
            TCGEN05_LD_32X32B_X16(r16, tmem + g * 16);
            TCGEN05_WAIT_LD();
            int row = wid * 32 + lane;
#pragma unroll
            for (int cc = 0; cc < 16; cc++)
                St[row * 17 + cc] = __uint_as_float(r16[cc]);
        }
        __syncthreads();
        {
            int col = bx * BNT + g * 16 + wc0;
            float o[8];
#pragma unroll
            for (int cc = 0; cc < 8; cc++) {
                float f = fmaxf(St[wrow * 17 + wc0 + cc], 0.f);
                if (mode == 1) f += rres[col + cc];
                o[cc] = f;
            }
            *(float4*)(Cb + col)     = make_float4(o[0], o[1], o[2], o[3]);
            *(float4*)(Cb + col + 4) = make_float4(o[4], o[5], o[6], o[7]);
        }
        __syncthreads();
    }
    TCGEN05_FENCE_BEFORE();
    if (wid == 0) TCGEN05_DEALLOC(tmem, BNT);

#else  // ---------------- FFMA fallback (generic PTX pass; never runs) -------
    constexpr int BK = 16, TM = 8, TN = 8;
    float* As = (float*)smem;
    float* Bs = (float*)(smem + 8192);
    int aRow0 = tid >> 2, aK0 = (tid & 3) << 2;
    int aRow1 = aRow0 + 64;
    const float* Xr0 = Abase + (size_t)aRow0 * K + aK0;
    const float* Xr1 = Abase + (size_t)aRow1 * K + aK0;
    int tx = tid & 15, ty = tid >> 4;
    for (int nh = 0; nh < BNT / 128; nh++) {
        int colbase = bx * BNT + nh * 128;
        const float* Wr0 = W + (size_t)(colbase + aRow0) * K + aK0;
        const float* Wr1 = W + (size_t)(colbase + aRow1) * K + aK0;
        float acc[TM][TN];
#pragma unroll
        for (int m = 0; m < TM; m++)
#pragma unroll
            for (int n = 0; n < TN; n++) acc[m][n] = 0.f;
        for (int k0 = 0; k0 < K; k0 += BK) {
            float4 a0 = *(const float4*)(Xr0 + k0);
            float4 a1 = *(const float4*)(Xr1 + k0);
            float4 b0 = *(const float4*)(Wr0 + k0);
            float4 b1 = *(const float4*)(Wr1 + k0);
            __syncthreads();
            As[(aK0 + 0) * 128 + aRow0] = a0.x; As[(aK0 + 1) * 128 + aRow0] = a0.y;
            As[(aK0 + 2) * 128 + aRow0] = a0.z; As[(aK0 + 3) * 128 + aRow0] = a0.w;
            As[(aK0 + 0) * 128 + aRow1] = a1.x; As[(aK0 + 1) * 128 + aRow1] = a1.y;
            As[(aK0 + 2) * 128 + aRow1] = a1.z; As[(aK0 + 3) * 128 + aRow1] = a1.w;
            Bs[(aK0 + 0) * 128 + aRow0] = b0.x; Bs[(aK0 + 1) * 128 + aRow0] = b0.y;
            Bs[(aK0 + 2) * 128 + aRow0] = b0.z; Bs[(aK0 + 3) * 128 + aRow0] = b0.w;
            Bs[(aK0 + 0) * 128 + aRow1] = b1.x; Bs[(aK0 + 1) * 128 + aRow1] = b1.y;
            Bs[(aK0 + 2) * 128 + aRow1] = b1.z; Bs[(aK0 + 3) * 128 + aRow1] = b1.w;
            __syncthreads();
#pragma unroll
            for (int k = 0; k < BK; k++) {
#pragma unroll
                for (int m = 0; m < TM; m++) {
                    float a = As[k * 128 + ty * TM + m];
#pragma unroll
                    for (int n = 0; n < TN; n++)
                        acc[m][n] = fmaf(a, Bs[k * 128 + tx * TN + n], acc[m][n]);
                }
            }
        }
        int lr0 = (mode == 0) ? (byg * NPTS + ty * TM) : (byl * NPTS + ty * TM);
        int col0 = colbase + tx * TN;
        float* Csel = (mode == 0) ? d_h : ((byg < 32) ? C0 : d_tmp);
        const float* Rsel = (mode == 1) ? ((byg < 32) ? R0 : R1) : nullptr;
#pragma unroll
        for (int m = 0; m < TM; m++) {
            int gr = lr0 + m;
            const float* rr = Rsel ? (Rsel + (size_t)gr * N) : nullptr;
#pragma unroll
            for (int n = 0; n < TN; n++) {
                float vv = fmaxf(acc[m][n], 0.f);
                if (rr) vv += rr[col0 + n];
                Csel[(size_t)gr * N + col0 + n] = vv;
            }
        }
        __syncthreads();
    }
#endif
}

// ------------------- JV Hungarian (colred + ARR + Dijkstra) ------------------
__device__ __forceinline__ unsigned fkey(float f) {
    unsigned u = __float_as_uint(f);
    return (u & 0x80000000u) ? ~u : (u | 0x80000000u);
}
__device__ __forceinline__ float fuk(unsigned k) {
    k = (k & 0x80000000u) ? (k & 0x7fffffffu) : ~k;
    return __uint_as_float(k);
}

__global__ void lap_kernel() {
    extern __shared__ float csh[];            // [128][128] cost, 64KB
    __shared__ float u_sh[NPTS];
    __shared__ int   roc_sh[NPTS];            // row of col (-1 free)
    __shared__ int   cor_sh[NPTS];            // col of row (-1 free)
    __shared__ int   way_sh[NPTS];
    __shared__ int   im_sh[NPTS];
    __shared__ int   fl_sh[192];              // ARR worklist
    __shared__ int   brd[3];
    __shared__ float brdf[1];
    int b = blockIdx.x, lane = threadIdx.x;

    const float4* src = (const float4*)(d_cost + (size_t)b * NPTS * NPTS);
    float4* dst = (float4*)csh;
    for (int i = lane; i < NPTS * NPTS / 4; i += 32) dst[i] = src[i];
    for (int r = lane; r < NPTS; r += 32) {
        u_sh[r] = 0.f; cor_sh[r] = -1; roc_sh[r] = -1;
    }
    __syncwarp();

    // ---- phase 1: column reduction + greedy assign ----
    float v[4] = {INFINITY, INFINITY, INFINITY, INFINITY};
    int im[4] = {0, 0, 0, 0};
    for (int i = 0; i < NPTS; i++) {
        float4 c4 = *(const float4*)(csh + i * NPTS + 4 * lane);
        float cc[4] = {c4.x, c4.y, c4.z, c4.w};
#pragma unroll
        for (int t = 0; t < 4; t++)
            if (cc[t] < v[t]) { v[t] = cc[t]; im[t] = i; }
    }
#pragma unroll
    for (int t = 0; t < 4; t++) im_sh[4 * lane + t] = im[t];
    __syncwarp();
    if (lane == 0) {
        for (int j = 0; j < NPTS; j++) {
            int i = im_sh[j];
            if (cor_sh[i] < 0) { cor_sh[i] = j; roc_sh[j] = i; }
        }
    }
    __syncwarp();

    // ---- phase 2: augmenting row reduction (lapjv ARR, step-capped) ----
    {
        int k = 0, nf = 0, steps = 0;        // lane0-authoritative
        if (lane == 0) {
            for (int r = 0; r < NPTS; r++) if (cor_sh[r] < 0) fl_sh[nf++] = r;
        }
        while (true) {
            if (lane == 0) brd[0] = (k < nf && steps < 3 * NPTS) ? fl_sh[k] : -1;
            __syncwarp();
            int i = brd[0];
            if (i < 0) break;
            steps++;
            // warp scan of row i: (min1, col1, min2, col2) of c[i][j]-v[j]
            float4 c4 = *(const float4*)(csh + i * NPTS + 4 * lane);
            float rr[4] = {c4.x - v[0], c4.y - v[1], c4.z - v[2], c4.w - v[3]};
            float m1 = rr[0], m2 = INFINITY;
            int j1l = 4 * lane, j2l = 4 * lane;
#pragma unroll
            for (int t = 1; t < 4; t++) {
                int j = 4 * lane + t;
                if (rr[t] < m1) { m2 = m1; j2l = j1l; m1 = rr[t]; j1l = j; }
                else if (rr[t] < m2) { m2 = rr[t]; j2l = j; }
            }
            for (int off = 16; off; off >>= 1) {
                float om1 = __shfl_down_sync(FULLM, m1, off);
                float om2 = __shfl_down_sync(FULLM, m2, off);
                int oj1 = __shfl_down_sync(FULLM, j1l, off);
                int oj2 = __shfl_down_sync(FULLM, j2l, off);
                if (om1 < m1) {
                    if (m1 < om2) { m2 = m1; j2l = j1l; }
                    else { m2 = om2; j2l = oj2; }
                    m1 = om1; j1l = oj1;
                } else if (om1 < m2) { m2 = om1; j2l = oj1; }
            }
            if (lane == 0) {
                float u1 = m1, u2 = m2;
                int j1 = j1l, dec = -1;
                if (u1 < u2) dec = j1;
                else if (roc_sh[j1] >= 0) j1 = j2l;
                int i0 = roc_sh[j1];
                if (i0 >= 0) {
                    cor_sh[i0] = -1;
                    if (u1 < u2) fl_sh[k] = i0;          // reprocess in place
                    else { if (nf < 192) fl_sh[nf++] = i0; k++; }
                } else k++;
                roc_sh[j1] = i; cor_sh[i] = j1;
                brd[1] = dec; brdf[0] = u2 - u1;
            }
            __syncwarp();
            int jd = brd[1];
            if (jd >= 0 && lane == (jd >> 2)) v[jd & 3] -= brdf[0];
        }
    }
    __syncwarp();
    // exact duals for matched rows: u[i] = c[i][cor[i]] - v[cor[i]]
#pragma unroll
    for (int t = 0; t < 4; t++) {
        int j = 4 * lane + t;
        int i = roc_sh[j];
        if (i >= 0) u_sh[i] = csh[i * NPTS + j] - v[t];
    }
    __syncwarp();

    // ---- phase 3: Dijkstra augmentation for remaining free rows ----
    int roc_r[4];
#pragma unroll
    for (int t = 0; t < 4; t++) roc_r[t] = roc_sh[4 * lane + t];

    for (int i = 0; i < NPTS; i++) {
        if (cor_sh[i] >= 0) continue;
        float dist[4] = {INFINITY, INFINITY, INFINITY, INFINITY};
        int usedm = 0;
        int i0 = i, j0 = -1, jfin = -1;
        float D = 0.f, ui0 = u_sh[i0];
        for (int it = 0; it < NPTS + 2; it++) {
            float4 c4 = *(const float4*)(csh + i0 * NPTS + 4 * lane);
            float cc[4] = {c4.x, c4.y, c4.z, c4.w};
            float best = INFINITY; int jb = 0x7ffffffc;
#pragma unroll
            for (int t = 0; t < 4; t++) {
                if (!((usedm >> t) & 1)) {
                    float nd = D + cc[t] - ui0 - v[t];
                    if (nd < dist[t]) { dist[t] = nd; way_sh[4 * lane + t] = j0; }
                    if (dist[t] < best) { best = dist[t]; jb = 4 * lane + t; }
                }
            }
            unsigned key = fkey(best);
            unsigned kmin = __reduce_min_sync(FULLM, key);
            unsigned bal = __ballot_sync(FULLM, key == kmin);
            int srcl = __ffs(bal) - 1;
            int ir = roc_r[jb & 3];               // owner's matched row for jb
            int j1 = __shfl_sync(FULLM, jb, srcl);
            int i1 = __shfl_sync(FULLM, ir, srcl);
            D = fuk(kmin);
            if (i1 < 0) { jfin = j1; break; }
            { int ol = j1 >> 2, ot = j1 & 3; if (lane == ol) usedm |= 1 << ot; }
            i0 = i1; ui0 = u_sh[i0]; j0 = j1;
        }
        __syncwarp();
#pragma unroll
        for (int t = 0; t < 4; t++) {
            if ((usedm >> t) & 1) {
                float dd = D - dist[t];
                v[t] -= dd;
                u_sh[roc_r[t]] += dd;
            }
        }
        if (lane == 0) u_sh[i] += D;
        __syncwarp();
        if (lane == 0) {
            int j = jfin;
            while (way_sh[j] >= 0) { int jp = way_sh[j]; roc_sh[j] = roc_sh[jp]; j = jp; }
            roc_sh[j] = i;
        }
        __syncwarp();
#pragma unroll
        for (int t = 0; t < 4; t++) roc_r[t] = roc_sh[4 * lane + t];
    }
    for (int j = lane; j < NPTS; j += 32)
        d_perm[b * NPTS + roc_sh[j]] = b * NPTS + j;
}

// --------------------------- out1 permutation gather ------------------------
__global__ void gather_kernel(float* __restrict__ out1) {
    int g = blockIdx.x;
    int src = d_perm[g];
    const float4* s = (const float4*)(d_tmp + (size_t)src * DIM);
    float4* d = (float4*)(out1 + (size_t)g * DIM);
    for (int k = threadIdx.x; k < DIM / 4; k += 256) d[k] = s[k];
}

// ------------------------------ launch --------------------------------------
static cudaStream_t g_s2 = nullptr;
static cudaEvent_t g_evF = nullptr, g_evJ = nullptr;

extern "C" void kernel_launch(void* const* d_in, const int* in_sizes, int n_in,
                              void* d_out, int out_size) {
    const float* support = (const float*)d_in[0];
    const float* query   = (const float*)d_in[1];
    const float* W1      = (const float*)d_in[2];   // [1024, 2048]
    const float* W2      = (const float*)d_in[3];   // [2048, 1024]
    float* out0 = (float*)d_out;
    float* out1 = out0 + (size_t)MROWS * DIM;

    if (!g_s2) {   // one-time resource creation (first call is uncaptured)
        cudaStreamCreateWithFlags(&g_s2, cudaStreamNonBlocking);   // NORMAL prio
        cudaEventCreateWithFlags(&g_evF, cudaEventDisableTiming);
        cudaEventCreateWithFlags(&g_evJ, cudaEventDisableTiming);
        cudaFuncSetAttribute(lap_kernel, cudaFuncAttributeMaxDynamicSharedMemorySize, 65536);
        cudaFuncSetAttribute(tgemm_kernel, cudaFuncAttributeMaxDynamicSharedMemorySize, TG_SMEM);
    }

    // fork: GEMM chain (independent of matching) runs on s2 concurrently
    cudaEventRecord(g_evF, 0);
    cudaStreamWaitEvent(g_s2, g_evF, 0);

    // stream 0: matching path (norms fused into cost)
    cost_kernel<<<dim3(4, BATCH), 256>>>(support, query);
    lap_kernel<<<BATCH, 32, 65536>>>();

    // stream s2: MLP, both branches merged per layer (R11 topology)
    tgemm_kernel<<<dim3(HID / BNT, 2 * BATCH), 256, TG_SMEM, g_s2>>>(
        support, query, W1, nullptr, nullptr, nullptr, HID, DIM, 0, 0);
    tgemm_kernel<<<dim3(DIM / BNT, 2 * BATCH), 256, TG_SMEM, g_s2>>>(
        nullptr, nullptr, W2, out0, support, query, DIM, HID, 1, 0);
    cudaEventRecord(g_evJ, g_s2);

    // join, then permute out1
    cudaStreamWaitEvent(0, g_evJ, 0);
    gather_kernel<<<MROWS, 256>>>(out1);
}

// round 15
// speedup vs baseline: 1.3365x; 1.3286x over previous
#include <cuda_runtime.h>
#include <math.h>
#include <stdint.h>

#define BATCH 32
#define NPTS  128
#define DIM   2048
#define HID   1024
#define MROWS (BATCH * NPTS)   // 4096
#define KC    32               // K floats per smem chunk (= 128B SW128 atom row)
#define BNT   256              // GEMM N tile
#define FULLM 0xffffffffu

// tcgen05 / f32x2 only exist in the sm_103a (arch-specific) compilation pass.
#ifdef __CUDA_ARCH_FEAT_SM103_ALL
#define HAS_TCGEN05 1
#endif

// ------------------------------ scratch ------------------------------------
__device__ float d_cost[BATCH * NPTS * NPTS];
__device__ int   d_perm[MROWS];                 // d_perm[g] = global src row of out1 row g
__device__ float d_h[2u * MROWS * HID];         // hidden acts: rows 0..4095 support, 4096..8191 query
__device__ float d_tmp[(size_t)MROWS * DIM];    // query + mlp(query), unpermuted

// ------------------------------ PTX helpers ---------------------------------
__device__ __forceinline__ uint32_t smem_u32(const void* p) {
    uint32_t a;
    asm("{ .reg .u64 t; cvta.to.shared.u64 t, %1; cvt.u32.u64 %0, t; }"
        : "=r"(a) : "l"(p));
    return a;
}
#define SW128(o) ((o) ^ (((o) >> 3) & 0x70))

#ifdef HAS_TCGEN05
__device__ __forceinline__ float to_tf32(float x) {
    float r; asm("cvt.rna.tf32.f32 %0, %1;" : "=f"(r) : "f"(x)); return r;
}
#define TCGEN05_ALLOC(smem_addr, nCols) \
    asm volatile("tcgen05.alloc.cta_group::1.sync.aligned.shared::cta.b32 [%0], %1;" \
        :: "r"((uint32_t)(smem_addr)), "r"((uint32_t)(nCols)) : "memory")
#define TCGEN05_DEALLOC(tmem_addr, nCols) \
    asm volatile("tcgen05.dealloc.cta_group::1.sync.aligned.b32 %0, %1;" \
        :: "r"(tmem_addr), "r"((uint32_t)(nCols)))
#define TCGEN05_RELINQUISH() \
    asm volatile("tcgen05.relinquish_alloc_permit.cta_group::1.sync.aligned;")
#define TCGEN05_COMMIT(mbar) \
    asm volatile("tcgen05.commit.cta_group::1.mbarrier::arrive::one.shared::cluster.b64 [%0];" \
        :: "r"((uint32_t)(mbar)) : "memory")
#define TCGEN05_FENCE_AFTER() \
    asm volatile("tcgen05.fence::after_thread_sync;" ::: "memory")
#define TCGEN05_FENCE_BEFORE() \
    asm volatile("tcgen05.fence::before_thread_sync;" ::: "memory")
#define TCGEN05_WAIT_LD() \
    asm volatile("tcgen05.wait::ld.sync.aligned;" ::: "memory")
#define TCGEN05_LD_32X32B_X16(r, tmem_addr) \
    asm volatile("tcgen05.ld.sync.aligned.32x32b.x16.b32 " \
        "{%0, %1, %2, %3, %4, %5, %6, %7, %8, %9, %10, %11, %12, %13, %14, %15}, [%16];" \
        : "=r"((r)[0]), "=r"((r)[1]), "=r"((r)[2]), "=r"((r)[3]), \
          "=r"((r)[4]), "=r"((r)[5]), "=r"((r)[6]), "=r"((r)[7]), \
          "=r"((r)[8]), "=r"((r)[9]), "=r"((r)[10]), "=r"((r)[11]), \
          "=r"((r)[12]), "=r"((r)[13]), "=r"((r)[14]), "=r"((r)[15]) \
        : "r"(tmem_addr))
#define MBARRIER_INIT(mbar, count) \
    asm volatile("mbarrier.init.shared.b64 [%0], %1;" \
        :: "r"((uint32_t)(mbar)), "r"((uint32_t)(count)) : "memory")
#define MBARRIER_WAIT_PARITY(mbar, parity) do { \
    uint32_t _m = (uint32_t)(mbar); uint32_t _p = (uint32_t)(parity); uint32_t _d; \
    asm volatile("{\n\t.reg .pred p;\n\t" \
        "mbarrier.try_wait.parity.acquire.cta.shared::cta.b64 p, [%1], %2;\n\t" \
        "selp.b32 %0, 1, 0, p;\n\t}" : "=r"(_d) : "r"(_m), "r"(_p) : "memory"); \
    if (!_d) { \
        asm volatile("{\n\t.reg .pred P1;\n\t" \
            "WL_%=:\n\t" \
            "mbarrier.try_wait.parity.acquire.cta.shared::cta.b64 P1, [%0], %1, 0x989680;\n\t" \
            "@P1 bra.uni WD_%=;\n\t" \
            "bra.uni WL_%=;\n\t" \
            "WD_%=:\n\t}" :: "r"(_m), "r"(_p) : "memory"); \
    } \
} while (0)

__device__ __forceinline__ void mma_tf32_ss(uint32_t d, uint64_t ad, uint64_t bd,
                                            uint32_t idesc, int acc) {
    asm volatile("{\n\t.reg .pred p;\n\t"
        "setp.ne.u32 p, %4, 0;\n\t"
        "tcgen05.mma.cta_group::1.kind::tf32 [%0], %1, %2, %3, {%5, %5, %5, %5}, p;\n\t"
        "}" :: "r"(d), "l"(ad), "l"(bd), "r"(idesc), "r"(acc), "r"(0u) : "memory");
}
// idesc: c=F32(1<<4), a=TF32(2<<7), b=TF32(2<<10), N=256(32<<17), M=128(8<<24)
#define IDESC_TF32 ((8u << 24) | ((BNT / 8u) << 17) | (2u << 10) | (2u << 7) | (1u << 4))

__device__ __forceinline__ uint64_t make_desc_sw128(uint32_t addr) {
    return ((uint64_t)2 << 61) | ((uint64_t)1 << 46) | ((uint64_t)64 << 32)
         | ((uint64_t)1 << 16) | ((addr >> 4) & 0x3FFF);
}

__device__ __forceinline__ void fma2(unsigned long long& d,
                                     unsigned long long a, unsigned long long b) {
    asm("fma.rn.f32x2 %0, %1, %2, %0;" : "+l"(d) : "l"(a), "l"(b));
}
#endif // HAS_TCGEN05

// ------------------------- cost (fp32) + fused norms -------------------------
__global__ void __launch_bounds__(256) cost_kernel(const float* __restrict__ S,
                                                   const float* __restrict__ Q) {
    constexpr int BN = 32, TM = 4, TN = 4;
    __shared__ float2 As2[8][NPTS];
    __shared__ float2 Bs2[8][BN];
    __shared__ float ns_sh[NPTS];
    __shared__ float nq_sh[BN];
    int b = blockIdx.y, cb = blockIdx.x;
    const float* Sb = S + (size_t)b * NPTS * DIM;
    const float* Qb = Q + (size_t)b * NPTS * DIM + (size_t)cb * BN * DIM;
    int tid = threadIdx.x;
    int aRow0 = tid >> 2, aK0 = (tid & 3) << 2;
    int aRow1 = aRow0 + 64;
    const float* Sr0 = Sb + (size_t)aRow0 * DIM + aK0;
    const float* Sr1 = Sb + (size_t)aRow1 * DIM + aK0;
    int bRow = tid >> 2;
    const float* Qr = Qb + (size_t)(bRow & 31) * DIM + aK0;
    int tx = tid & 7, ty = tid >> 3;
    int kk0 = aK0 >> 1;
    float sn0 = 0.f, sn1 = 0.f, qn = 0.f;

#ifdef HAS_TCGEN05
    unsigned long long acc2[TM][TN];
#pragma unroll
    for (int m = 0; m < TM; m++)
#pragma unroll
        for (int n = 0; n < TN; n++) acc2[m][n] = 0ull;

    for (int k0 = 0; k0 < DIM; k0 += 16) {
        float4 a0 = *(const float4*)(Sr0 + k0);
        float4 a1 = *(const float4*)(Sr1 + k0);
        float4 b0 = (bRow < 32) ? *(const float4*)(Qr + k0) : make_float4(0, 0, 0, 0);
        sn0 = fmaf(a0.x, a0.x, sn0); sn0 = fmaf(a0.y, a0.y, sn0);
        sn0 = fmaf(a0.z, a0.z, sn0); sn0 = fmaf(a0.w, a0.w, sn0);
        sn1 = fmaf(a1.x, a1.x, sn1); sn1 = fmaf(a1.y, a1.y, sn1);
        sn1 = fmaf(a1.z, a1.z, sn1); sn1 = fmaf(a1.w, a1.w, sn1);
        qn  = fmaf(b0.x, b0.x, qn);  qn  = fmaf(b0.y, b0.y, qn);
        qn  = fmaf(b0.z, b0.z, qn);  qn  = fmaf(b0.w, b0.w, qn);
        __syncthreads();
        As2[kk0][aRow0] = make_float2(a0.x, a0.y);
        As2[kk0 + 1][aRow0] = make_float2(a0.z, a0.w);
        As2[kk0][aRow1] = make_float2(a1.x, a1.y);
        As2[kk0 + 1][aRow1] = make_float2(a1.z, a1.w);
        if (bRow < 32) {
            Bs2[kk0][bRow] = make_float2(b0.x, b0.y);
            Bs2[kk0 + 1][bRow] = make_float2(b0.z, b0.w);
        }
        __syncthreads();
#pragma unroll
        for (int kk = 0; kk < 8; kk++) {
            unsigned long long a2[TM], b2[TN];
#pragma unroll
            for (int m = 0; m < TM; m++)
                a2[m] = *(const unsigned long long*)&As2[kk][ty * TM + m];
#pragma unroll
            for (int n = 0; n < TN; n++)
                b2[n] = *(const unsigned long long*)&Bs2[kk][tx * TN + n];
#pragma unroll
            for (int m = 0; m < TM; m++)
#pragma unroll
                for (int n = 0; n < TN; n++) fma2(acc2[m][n], a2[m], b2[n]);
        }
    }
    sn0 += __shfl_xor_sync(FULLM, sn0, 1); sn0 += __shfl_xor_sync(FULLM, sn0, 2);
    sn1 += __shfl_xor_sync(FULLM, sn1, 1); sn1 += __shfl_xor_sync(FULLM, sn1, 2);
    qn  += __shfl_xor_sync(FULLM, qn, 1);  qn  += __shfl_xor_sync(FULLM, qn, 2);
    if ((tid & 3) == 0) {
        ns_sh[aRow0] = sn0; ns_sh[aRow1] = sn1;
        if (bRow < 32) nq_sh[bRow] = qn;
    }
    __syncthreads();
#pragma unroll
    for (int m = 0; m < TM; m++) {
        int r = ty * TM + m;
        float ni = sqrtf(ns_sh[r]);
#pragma unroll
        for (int n = 0; n < TN; n++) {
            int cl = tx * TN + n;
            float nj = sqrtf(nq_sh[cl]);
            float lo = __uint_as_float((unsigned)(acc2[m][n] & 0xffffffffull));
            float hi = __uint_as_float((unsigned)(acc2[m][n] >> 32));
            d_cost[(size_t)b * NPTS * NPTS + r * NPTS + cb * BN + cl] =
                1.0f - (lo + hi) / (ni * nj);
        }
    }
#else
    float acc[TM][TN];
#pragma unroll
    for (int m = 0; m < TM; m++)
#pragma unroll
        for (int n = 0; n < TN; n++) acc[m][n] = 0.f;
    for (int k0 = 0; k0 < DIM; k0 += 16) {
        float4 a0 = *(const float4*)(Sr0 + k0);
        float4 a1 = *(const float4*)(Sr1 + k0);
        float4 b0 = (bRow < 32) ? *(const float4*)(Qr + k0) : make_float4(0, 0, 0, 0);
        sn0 = fmaf(a0.x, a0.x, sn0); sn0 = fmaf(a0.y, a0.y, sn0);
        sn0 = fmaf(a0.z, a0.z, sn0); sn0 = fmaf(a0.w, a0.w, sn0);
        sn1 = fmaf(a1.x, a1.x, sn1); sn1 = fmaf(a1.y, a1.y, sn1);
        sn1 = fmaf(a1.z, a1.z, sn1); sn1 = fmaf(a1.w, a1.w, sn1);
        qn  = fmaf(b0.x, b0.x, qn);  qn  = fmaf(b0.y, b0.y, qn);
        qn  = fmaf(b0.z, b0.z, qn);  qn  = fmaf(b0.w, b0.w, qn);
        __syncthreads();
        As2[kk0][aRow0] = make_float2(a0.x, a0.y);
        As2[kk0 + 1][aRow0] = make_float2(a0.z, a0.w);
        As2[kk0][aRow1] = make_float2(a1.x, a1.y);
        As2[kk0 + 1][aRow1] = make_float2(a1.z, a1.w);
        if (bRow < 32) {
            Bs2[kk0][bRow] = make_float2(b0.x, b0.y);
            Bs2[kk0 + 1][bRow] = make_float2(b0.z, b0.w);
        }
        __syncthreads();
#pragma unroll
        for (int kk = 0; kk < 8; kk++) {
#pragma unroll
            for (int m = 0; m < TM; m++) {
                float2 a = As2[kk][ty * TM + m];
#pragma unroll
                for (int n = 0; n < TN; n++) {
                    float2 bb = Bs2[kk][tx * TN + n];
                    acc[m][n] = fmaf(a.x, bb.x, acc[m][n]);
                    acc[m][n] = fmaf(a.y, bb.y, acc[m][n]);
                }
            }
        }
    }
    sn0 += __shfl_xor_sync(FULLM, sn0, 1); sn0 += __shfl_xor_sync(FULLM, sn0, 2);
    sn1 += __shfl_xor_sync(FULLM, sn1, 1); sn1 += __shfl_xor_sync(FULLM, sn1, 2);
    qn  += __shfl_xor_sync(FULLM, qn, 1);  qn  += __shfl_xor_sync(FULLM, qn, 2);
    if ((tid & 3) == 0) {
        ns_sh[aRow0] = sn0; ns_sh[aRow1] = sn1;
        if (bRow < 32) nq_sh[bRow] = qn;
    }
    __syncthreads();
#pragma unroll
    for (int m = 0; m < TM; m++) {
        int r = ty * TM + m;
        float ni = sqrtf(ns_sh[r]);
#pragma unroll
        for (int n = 0; n < TN; n++) {
            int cl = tx * TN + n;
            float nj = sqrtf(nq_sh[cl]);
            d_cost[(size_t)b * NPTS * NPTS + r * NPTS + cb * BN + cl] =
                1.0f - acc[m][n] / (ni * nj);
        }
    }
#endif
}

// ------------------------- merged MLP GEMM (128 x 256 tile) ------------------
#define TG_SMEM (1024 + 2 * 49152)
__global__ void __launch_bounds__(256, 2)
tgemm_kernel(const float* __restrict__ A0, const float* __restrict__ A1,
             const float* __restrict__ W, float* __restrict__ C0,
             const float* __restrict__ R0, const float* __restrict__ R1,
             int N, int K, int mode, int yoff) {
    extern __shared__ char smem[];
    int tid = threadIdx.x;
    int bx = blockIdx.x, byg = blockIdx.y + yoff;
    int byl = byg & 31;
    const float* Abase;
    if (mode == 0)
        Abase = (byg < 32) ? (A0 + (size_t)byg * NPTS * K)
                           : (A1 + (size_t)(byg - 32) * NPTS * K);
    else
        Abase = d_h + (size_t)byg * NPTS * K;

#ifdef HAS_TCGEN05
    uint32_t sb = smem_u32(smem);
    int wid = tid >> 5, lane = tid & 31;

    if (wid == 0) {
        TCGEN05_ALLOC(sb, BNT);
        TCGEN05_RELINQUISH();          // release permit NOW (occ 2)
    }
    if (tid == 0) { MBARRIER_INIT(sb + 8, 1); MBARRIER_INIT(sb + 16, 1); }
    __syncthreads();
    uint32_t tmem;
    asm volatile("ld.shared.b32 %0, [%1];" : "=r"(tmem) : "r"(sb));

    int r0 = tid >> 3, kg = tid & 7;
    const float* ap0 = Abase + (size_t)r0 * K + kg * 4;
    const float* bp0 = W + (size_t)(bx * BNT + r0) * K + kg * 4;
    uint32_t soff0 = SW128((uint32_t)(r0 * 128 + kg * 16));
    size_t astep = (size_t)32 * K;

    uint64_t adesc[2] = { make_desc_sw128(sb + 1024),
                          make_desc_sw128(sb + 1024 + 49152) };
    uint64_t bdesc[2] = { make_desc_sw128(sb + 1024 + 16384),
                          make_desc_sw128(sb + 1024 + 49152 + 16384) };

    const int NCH = K / KC;
    float4 a4[4], b4[8], an[4], bn[8];
#pragma unroll
    for (int i = 0; i < 4; i++) a4[i] = *(const float4*)(ap0 + i * astep);
#pragma unroll
    for (int i = 0; i < 8; i++) b4[i] = *(const float4*)(bp0 + i * astep);
    for (int c = 0; c < NCH; c++) {
        int s = c & 1;
        uint32_t stg = 1024 + (uint32_t)s * 49152;
        if (c + 1 < NCH) {
            const float* apn = ap0 + (size_t)(c + 1) * KC;
            const float* bpn = bp0 + (size_t)(c + 1) * KC;
#pragma unroll
            for (int i = 0; i < 4; i++) an[i] = *(const float4*)(apn + i * astep);
#pragma unroll
            for (int i = 0; i < 8; i++) bn[i] = *(const float4*)(bpn + i * astep);
        }
        if (c >= 2) MBARRIER_WAIT_PARITY(sb + 8 + 8 * s, ((c >> 1) - 1) & 1);
#pragma unroll
        for (int i = 0; i < 4; i++) {
            float4 t;
            t.x = to_tf32(a4[i].x); t.y = to_tf32(a4[i].y);
            t.z = to_tf32(a4[i].z); t.w = to_tf32(a4[i].w);
            *(float4*)(smem + stg + soff0 + i * 4096u) = t;
        }
#pragma unroll
        for (int i = 0; i < 8; i++) {
            float4 t;
            t.x = to_tf32(b4[i].x); t.y = to_tf32(b4[i].y);
            t.z = to_tf32(b4[i].z); t.w = to_tf32(b4[i].w);
            *(float4*)(smem + stg + 16384 + soff0 + i * 4096u) = t;
        }
        __syncthreads();
        if (tid == 0) {
            asm volatile("fence.proxy.async.shared::cta;" ::: "memory");
#pragma unroll
            for (int k = 0; k < 4; k++)
                mma_tf32_ss(tmem, adesc[s] + k * 2, bdesc[s] + k * 2, IDESC_TF32, (c | k) != 0);
            TCGEN05_COMMIT(sb + 8 + 8 * s);
        }
#pragma unroll
        for (int i = 0; i < 4; i++) a4[i] = an[i];
#pragma unroll
        for (int i = 0; i < 8; i++) b4[i] = bn[i];
    }
    MBARRIER_WAIT_PARITY(sb + 8 + 8 * ((NCH - 1) & 1), ((NCH - 1) >> 1) & 1);
    TCGEN05_FENCE_AFTER();

    float* St = (float*)(smem + 1024);
    int wrow = tid >> 1, wc0 = (tid & 1) * 8;
    float* Cb; const float* rres = nullptr;
    if (mode == 0) {
        Cb = d_h + (size_t)(byg * NPTS + wrow) * N;
    } else {
        size_t lr = (size_t)(byl * NPTS + wrow);
        Cb = ((byg < 32) ? C0 : d_tmp) + lr * N;
        rres = ((byg < 32) ? R0 : R1) + lr * N;
    }
    for (int g = 0; g < BNT / 16; g++) {
        if (tid < 128) {
            uint32_t r16[16];
            TCGEN05_LD_32X32B_X16(r16, tmem + g * 16);
            TCGEN05_WAIT_LD();
            int row = wid * 32 + lane;
#pragma unroll
            for (int cc = 0; cc < 16; cc++)
                St[row * 17 + cc] = __uint_as_float(r16[cc]);
        }
        __syncthreads();
        {
            int col = bx * BNT + g * 16 + wc0;
            float o[8];
#pragma unroll
            for (int cc = 0; cc < 8; cc++) {
                float f = fmaxf(St[wrow * 17 + wc0 + cc], 0.f);
                if (mode == 1) f += rres[col + cc];
                o[cc] = f;
            }
            *(float4*)(Cb + col)     = make_float4(o[0], o[1], o[2], o[3]);
            *(float4*)(Cb + col + 4) = make_float4(o[4], o[5], o[6], o[7]);
        }
        __syncthreads();
    }
    TCGEN05_FENCE_BEFORE();
    if (wid == 0) TCGEN05_DEALLOC(tmem, BNT);

#else  // ---------------- FFMA fallback (generic PTX pass; never runs) -------
    constexpr int BK = 16, TM = 8, TN = 8;
    float* As = (float*)smem;
    float* Bs = (float*)(smem + 8192);
    int aRow0 = tid >> 2, aK0 = (tid & 3) << 2;
    int aRow1 = aRow0 + 64;
    const float* Xr0 = Abase + (size_t)aRow0 * K + aK0;
    const float* Xr1 = Abase + (size_t)aRow1 * K + aK0;
    int tx = tid & 15, ty = tid >> 4;
    for (int nh = 0; nh < BNT / 128; nh++) {
        int colbase = bx * BNT + nh * 128;
        const float* Wr0 = W + (size_t)(colbase + aRow0) * K + aK0;
        const float* Wr1 = W + (size_t)(colbase + aRow1) * K + aK0;
        float acc[TM][TN];
#pragma unroll
        for (int m = 0; m < TM; m++)
#pragma unroll
            for (int n = 0; n < TN; n++) acc[m][n] = 0.f;
        for (int k0 = 0; k0 < K; k0 += BK) {
            float4 a0 = *(const float4*)(Xr0 + k0);
            float4 a1 = *(const float4*)(Xr1 + k0);
            float4 b0 = *(const float4*)(Wr0 + k0);
            float4 b1 = *(const float4*)(Wr1 + k0);
            __syncthreads();
            As[(aK0 + 0) * 128 + aRow0] = a0.x; As[(aK0 + 1) * 128 + aRow0] = a0.y;
            As[(aK0 + 2) * 128 + aRow0] = a0.z; As[(aK0 + 3) * 128 + aRow0] = a0.w;
            As[(aK0 + 0) * 128 + aRow1] = a1.x; As[(aK0 + 1) * 128 + aRow1] = a1.y;
            As[(aK0 + 2) * 128 + aRow1] = a1.z; As[(aK0 + 3) * 128 + aRow1] = a1.w;
            Bs[(aK0 + 0) * 128 + aRow0] = b0.x; Bs[(aK0 + 1) * 128 + aRow0] = b0.y;
            Bs[(aK0 + 2) * 128 + aRow0] = b0.z; Bs[(aK0 + 3) * 128 + aRow0] = b0.w;
            Bs[(aK0 + 0) * 128 + aRow1] = b1.x; Bs[(aK0 + 1) * 128 + aRow1] = b1.y;
            Bs[(aK0 + 2) * 128 + aRow1] = b1.z; Bs[(aK0 + 3) * 128 + aRow1] = b1.w;
            __syncthreads();
#pragma unroll
            for (int k = 0; k < BK; k++) {
#pragma unroll
                for (int m = 0; m < TM; m++) {
                    float a = As[k * 128 + ty * TM + m];
#pragma unroll
                    for (int n = 0; n < TN; n++)
                        acc[m][n] = fmaf(a, Bs[k * 128 + tx * TN + n], acc[m][n]);
                }
            }
        }
        int lr0 = (mode == 0) ? (byg * NPTS + ty * TM) : (byl * NPTS + ty * TM);
        int col0 = colbase + tx * TN;
        float* Csel = (mode == 0) ? d_h : ((byg < 32) ? C0 : d_tmp);
        const float* Rsel = (mode == 1) ? ((byg < 32) ? R0 : R1) : nullptr;
#pragma unroll
        for (int m = 0; m < TM; m++) {
            int gr = lr0 + m;
            const float* rr = Rsel ? (Rsel + (size_t)gr * N) : nullptr;
#pragma unroll
            for (int n = 0; n < TN; n++) {
                float vv = fmaxf(acc[m][n], 0.f);
                if (rr) vv += rr[col0 + n];
                Csel[(size_t)gr * N + col0 + n] = vv;
            }
        }
        __syncthreads();
    }
#endif
}

// ------------- JV Hungarian (colred + greedy + Dijkstra, fast bcast) --------
__device__ __forceinline__ unsigned fkey(float f) {
    unsigned u = __float_as_uint(f);
    return (u & 0x80000000u) ? ~u : (u | 0x80000000u);
}
__device__ __forceinline__ float fuk(unsigned k) {
    k = (k & 0x80000000u) ? (k & 0x7fffffffu) : ~k;
    return __uint_as_float(k);
}

__global__ void lap_kernel() {
    extern __shared__ float csh[];            // [128][128] cost, 64KB
    __shared__ float u_sh[NPTS];
    __shared__ int   roc_sh[NPTS];            // row of col (-1 free)
    __shared__ int   cor_sh[NPTS];            // col of row (-1 free)
    __shared__ int   way_sh[NPTS];
    __shared__ int   im_sh[NPTS];
    int b = blockIdx.x, lane = threadIdx.x;

    const float4* src = (const float4*)(d_cost + (size_t)b * NPTS * NPTS);
    float4* dst = (float4*)csh;
    for (int i = lane; i < NPTS * NPTS / 4; i += 32) dst[i] = src[i];
    for (int r = lane; r < NPTS; r += 32) {
        u_sh[r] = 0.f; cor_sh[r] = -1; roc_sh[r] = -1;
    }
    __syncwarp();

    // ---- phase 1: column reduction + greedy assign ----
    float v[4] = {INFINITY, INFINITY, INFINITY, INFINITY};
    int im[4] = {0, 0, 0, 0};
    for (int i = 0; i < NPTS; i++) {
        float4 c4 = *(const float4*)(csh + i * NPTS + 4 * lane);
        float cc[4] = {c4.x, c4.y, c4.z, c4.w};
#pragma unroll
        for (int t = 0; t < 4; t++)
            if (cc[t] < v[t]) { v[t] = cc[t]; im[t] = i; }
    }
#pragma unroll
    for (int t = 0; t < 4; t++) im_sh[4 * lane + t] = im[t];
    __syncwarp();
    if (lane == 0) {
        for (int j = 0; j < NPTS; j++) {
            int i = im_sh[j];
            if (cor_sh[i] < 0) { cor_sh[i] = j; roc_sh[j] = i; }
        }
    }
    __syncwarp();

    // ---- phase 2: Dijkstra augmentation for each free row ----
    int roc_r[4];
#pragma unroll
    for (int t = 0; t < 4; t++) roc_r[t] = roc_sh[4 * lane + t];

    for (int i = 0; i < NPTS; i++) {
        if (cor_sh[i] >= 0) continue;
        float dist[4] = {INFINITY, INFINITY, INFINITY, INFINITY};
        int usedm = 0;
        int i0 = i, j0 = -1, jfin = -1;
        float D = 0.f, ui0 = u_sh[i0];
        for (int it = 0; it < NPTS + 2; it++) {
            float4 c4 = *(const float4*)(csh + i0 * NPTS + 4 * lane);
            float cc[4] = {c4.x, c4.y, c4.z, c4.w};
            float best = INFINITY; int jb = 127; int irb = -1;
#pragma unroll
            for (int t = 0; t < 4; t++) {
                if (!((usedm >> t) & 1)) {
                    float nd = D + cc[t] - ui0 - v[t];
                    if (nd < dist[t]) { dist[t] = nd; way_sh[4 * lane + t] = j0; }
                    if (dist[t] < best) { best = dist[t]; jb = 4 * lane + t; irb = roc_r[t]; }
                }
            }
            // one REDUX for the min key, one REDUX broadcasting (col, matched row)
            unsigned key = fkey(best);
            unsigned kmin = __reduce_min_sync(FULLM, key);
            unsigned packed = (key == kmin)
                ? (((unsigned)jb << 8) | (unsigned)(irb + 1)) : 0xffffffffu;
            unsigned pmin = __reduce_min_sync(FULLM, packed);
            int j1 = (int)(pmin >> 8);
            int i1 = (int)(pmin & 0xffu) - 1;
            D = fuk(kmin);
            if (i1 < 0) { jfin = j1; break; }
            { int ol = j1 >> 2, ot = j1 & 3; if (lane == ol) usedm |= 1 << ot; }
            i0 = i1; ui0 = u_sh[i0]; j0 = j1;
        }
        __syncwarp();
#pragma unroll
        for (int t = 0; t < 4; t++) {
            if ((usedm >> t) & 1) {
                float dd = D - dist[t];
                v[t] -= dd;
                u_sh[roc_r[t]] += dd;
            }
        }
        if (lane == 0) u_sh[i] += D;
        __syncwarp();
        if (lane == 0) {
            int j = jfin;
            while (way_sh[j] >= 0) { int jp = way_sh[j]; roc_sh[j] = roc_sh[jp]; j = jp; }
            roc_sh[j] = i;
        }
        __syncwarp();
#pragma unroll
        for (int t = 0; t < 4; t++) roc_r[t] = roc_sh[4 * lane + t];
    }
    for (int j = lane; j < NPTS; j += 32)
        d_perm[b * NPTS + roc_sh[j]] = b * NPTS + j;
}

// --------------------------- out1 permutation gather ------------------------
__global__ void gather_kernel(float* __restrict__ out1) {
    int g = blockIdx.x;
    int src = d_perm[g];
    const float4* s = (const float4*)(d_tmp + (size_t)src * DIM);
    float4* d = (float4*)(out1 + (size_t)g * DIM);
    for (int k = threadIdx.x; k < DIM / 4; k += 256) d[k] = s[k];
}

// ------------------------------ launch --------------------------------------
static cudaStream_t g_s2 = nullptr;
static cudaEvent_t g_evF = nullptr, g_evJ = nullptr;

extern "C" void kernel_launch(void* const* d_in, const int* in_sizes, int n_in,
                              void* d_out, int out_size) {
    const float* support = (const float*)d_in[0];
    const float* query   = (const float*)d_in[1];
    const float* W1      = (const float*)d_in[2];   // [1024, 2048]
    const float* W2      = (const float*)d_in[3];   // [2048, 1024]
    float* out0 = (float*)d_out;
    float* out1 = out0 + (size_t)MROWS * DIM;

    if (!g_s2) {   // one-time resource creation (first call is uncaptured)
        cudaStreamCreateWithFlags(&g_s2, cudaStreamNonBlocking);   // NORMAL prio
        cudaEventCreateWithFlags(&g_evF, cudaEventDisableTiming);
        cudaEventCreateWithFlags(&g_evJ, cudaEventDisableTiming);
        cudaFuncSetAttribute(lap_kernel, cudaFuncAttributeMaxDynamicSharedMemorySize, 65536);
        cudaFuncSetAttribute(tgemm_kernel, cudaFuncAttributeMaxDynamicSharedMemorySize, TG_SMEM);
    }

    // fork: GEMM chain (independent of matching) runs on s2 concurrently
    cudaEventRecord(g_evF, 0);
    cudaStreamWaitEvent(g_s2, g_evF, 0);

    // stream 0: matching path (norms fused into cost)
    cost_kernel<<<dim3(4, BATCH), 256>>>(support, query);
    lap_kernel<<<BATCH, 32, 65536>>>();

    // stream s2: MLP, both branches merged per layer
    tgemm_kernel<<<dim3(HID / BNT, 2 * BATCH), 256, TG_SMEM, g_s2>>>(
        support, query, W1, nullptr, nullptr, nullptr, HID, DIM, 0, 0);
    tgemm_kernel<<<dim3(DIM / BNT, 2 * BATCH), 256, TG_SMEM, g_s2>>>(
        nullptr, nullptr, W2, out0, support, query, DIM, HID, 1, 0);
    cudaEventRecord(g_evJ, g_s2);

    // join, then permute out1
    cudaStreamWaitEvent(0, g_evJ, 0);
    gather_kernel<<<MROWS, 256>>>(out1);
}